// round 10
// baseline (speedup 1.0000x reference)
#include <cuda_runtime.h>
#include <math.h>

#define N_NODES 100000
#define N_EDGES 200000
#define H 128
#define H2 256
#define H3 384
#define NLVL 7
#define NBUCK_E 42        // z*21 + (l-1)*3 + gi ; z=1 -> hf[src] statically zero
#define NBUCK_N 21        // (l-1)*3 + gi
#define MSG_TE 32         // edges per msg tile
#define GRU_TN 16         // nodes per gru tile

// ---------------- device scratch (static: no allocations allowed) ----------
__device__ float g_msg[(size_t)N_NODES * H];   // scatter-add target
__device__ float g_hs_type[6 * H];             // per-gate-type hs row
__device__ float g_hsl1[3 * 6 * H];            // layer1 hs-half table [gi][gtype][j]
__device__ float g_wihT[3 * H * H3];           // transposed GRU input weights [gi][k][row]
__device__ int g_ecount[NBUCK_E];
__device__ int g_eoff[NBUCK_E + 1];
__device__ int g_ecur[NBUCK_E];
__device__ int g_etile[NBUCK_E + 1];
__device__ int g_ncount[NBUCK_N];
__device__ int g_noff[NBUCK_N + 1];
__device__ int g_ncur[NBUCK_N];
__device__ int g_ntile[NBUCK_N + 1];
__device__ int g_elist[N_EDGES];
__device__ int g_nlist[N_NODES];

__device__ __forceinline__ int gate_gi(int g) {
    // GATE_CODES = (3, 2, 5) -> gi 0, 1, 2
    return (g == 3) ? 0 : (g == 2) ? 1 : (g == 5) ? 2 : -1;
}

// edge bucket: z*21 + (l-1)*3 + gi   (z=1: hf[src] statically zero)
__device__ __forceinline__ int edge_bucket(int src, int dst,
                                           const int* gate, const int* lvl) {
    int gi = gate_gi(gate[dst]);
    int l = lvl[dst];
    if (gi < 0 || l < 1 || l > NLVL) return -1;
    int gs = gate_gi(gate[src]);
    int ls = lvl[src];
    int z = !(gs >= 0 && ls >= 1 && ls < l);
    return z * 21 + (l - 1) * 3 + gi;
}

// ---------------- setup kernels -------------------------------------------

// hs_type + bucket-count init (independent, fused to save a launch)
__global__ void k_hs_type(const float* __restrict__ Ws, const float* __restrict__ Wt,
                          const float* __restrict__ hsW, const float* __restrict__ hsb) {
    int g = blockIdx.x;      // 0..5
    int j = threadIdx.x;     // 0..127
    if (g == 0 && j < NBUCK_E) g_ecount[j] = 0;
    if (g == 1 && j < NBUCK_N) g_ncount[j] = 0;
    float acc = hsb[j];
#pragma unroll 4
    for (int k = 0; k < H; k++)
        acc = fmaf(Ws[g * H + k], hsW[k * H + j], acc);
#pragma unroll 4
    for (int k = 0; k < H; k++)
        acc = fmaf(Wt[g * H + k], hsW[(H + k) * H + j], acc);
    g_hs_type[g * H + j] = acc;
}

// layer1 hs-half table: hsl1[gi][g][j] = sum_k hs_type[g][k] * w1[gi][k][j]
__global__ void k_hsl1(const float* __restrict__ w1) {
    int gi = blockIdx.x;     // 0..2
    int g = blockIdx.y;      // 0..5
    int j = threadIdx.x;     // 0..127
    const float* w = w1 + (size_t)gi * H2 * H;
    float acc = 0.f;
#pragma unroll 4
    for (int k = 0; k < H; k++)
        acc = fmaf(g_hs_type[g * H + k], w[k * H + j], acc);
    g_hsl1[(gi * 6 + g) * H + j] = acc;
}

// transpose GRU input weights: wihT[gi][k][r] = wih[gi][r][k]
__global__ void k_transpose(const float* __restrict__ wih) {
    const int total = 3 * H3 * H;
    for (int i = blockIdx.x * blockDim.x + threadIdx.x; i < total; i += gridDim.x * blockDim.x) {
        int gi = i / (H3 * H);
        int rem = i - gi * (H3 * H);
        int r = rem / H;
        int k = rem - r * H;
        g_wihT[gi * H * H3 + k * H3 + r] = wih[i];
    }
}

// write hs to out[0:NH), zero hf region out[NH:2NH), zero msg buffer (float4)
__global__ void k_hs_fill(float4* __restrict__ out4, const int* __restrict__ gate) {
    const int total4 = N_NODES * (H / 4);
    const float4* hs4 = (const float4*)g_hs_type;
    float4* msg4 = (float4*)g_msg;
    const float4 z4 = make_float4(0.f, 0.f, 0.f, 0.f);
    for (int i = blockIdx.x * blockDim.x + threadIdx.x; i < total4; i += gridDim.x * blockDim.x) {
        int node = i >> 5;               // H/4 = 32 float4 per row
        int c = i & 31;
        out4[i] = hs4[gate[node] * 32 + c];
        out4[total4 + i] = z4;
        msg4[i] = z4;
    }
}

// count edges/nodes per bucket
__global__ void k_count(const int* __restrict__ ei, const int* __restrict__ gate,
                        const int* __restrict__ lvl) {
    const int total = N_EDGES + N_NODES;
    for (int i = blockIdx.x * blockDim.x + threadIdx.x; i < total; i += gridDim.x * blockDim.x) {
        if (i < N_EDGES) {
            int b = edge_bucket(ei[i], ei[N_EDGES + i], gate, lvl);
            if (b >= 0) atomicAdd(&g_ecount[b], 1);
        } else {
            int n = i - N_EDGES;
            int gi = gate_gi(gate[n]);
            int l = lvl[n];
            if (gi >= 0 && l >= 1 && l <= NLVL) atomicAdd(&g_ncount[(l - 1) * 3 + gi], 1);
        }
    }
}

__global__ void k_scan() {
    if (threadIdx.x == 0) {
        int s = 0, st = 0;
        for (int b = 0; b < NBUCK_E; b++) {
            g_eoff[b] = s; g_ecur[b] = s; g_etile[b] = st;
            st += (g_ecount[b] + MSG_TE - 1) / MSG_TE;
            s += g_ecount[b];
        }
        g_eoff[NBUCK_E] = s; g_etile[NBUCK_E] = st;
        s = 0; st = 0;
        for (int b = 0; b < NBUCK_N; b++) {
            g_noff[b] = s; g_ncur[b] = s; g_ntile[b] = st;
            st += (g_ncount[b] + GRU_TN - 1) / GRU_TN;
            s += g_ncount[b];
        }
        g_noff[NBUCK_N] = s; g_ntile[NBUCK_N] = st;
    }
}

__global__ void k_fill_lists(const int* __restrict__ ei, const int* __restrict__ gate,
                             const int* __restrict__ lvl) {
    const int total = N_EDGES + N_NODES;
    for (int i = blockIdx.x * blockDim.x + threadIdx.x; i < total; i += gridDim.x * blockDim.x) {
        if (i < N_EDGES) {
            int b = edge_bucket(ei[i], ei[N_EDGES + i], gate, lvl);
            if (b >= 0) {
                int pos = atomicAdd(&g_ecur[b], 1);
                g_elist[pos] = i;
            }
        } else {
            int n = i - N_EDGES;
            int gi = gate_gi(gate[n]);
            int l = lvl[n];
            if (gi >= 0 && l >= 1 && l <= NLVL) {
                int pos = atomicAdd(&g_ncur[(l - 1) * 3 + gi], 1);
                g_nlist[pos] = n;
            }
        }
    }
}

// ---------------- message kernel over a bucket range ----------------------
// Processes edge buckets [bBase, bBase+bCnt). Bucket id encodes z (hf zero?)
// and gi. Block = 128 threads, tile = 32 edges; thread owns cols (c0, c0+64)
// x 16 edges. layer1 = hsl1[gate[src]] (+ hf[src] @ w1[128:256] if z==0) + b1.
__global__ void __launch_bounds__(128) k_msg_range(
        const int* __restrict__ ei, const int* __restrict__ gate,
        const float* __restrict__ outbuf,
        const float* __restrict__ w1a, const float* __restrict__ b1a,
        const float* __restrict__ w2a, const float* __restrict__ b2a,
        const float* __restrict__ w3a, const float* __restrict__ b3a,
        int bBase, int bCnt) {
    __shared__ float4 hfs4[MSG_TE][H / 4];   // 16 KB: hf[src] stage (z==0 only)
    __shared__ float4 h14[MSG_TE][H / 4];    // 16 KB
    __shared__ float4 h24[MSG_TE][H / 4];    // 16 KB
    __shared__ int ssrc[MSG_TE];
    __shared__ int sdst[MSG_TE];
    __shared__ int sgt[MSG_TE];              // gate[src]

    const int t0 = g_etile[bBase];
    const int tN = g_etile[bBase + bCnt];
    const int tid = threadIdx.x;
    const int lane = tid & 31, wrp = tid >> 5;
    const int c0 = tid & 63;                 // cols c0 and c0+64
    const int eh = tid >> 6;                 // edge half: 0 or 1
    const float* hf = outbuf + (size_t)N_NODES * H;

    for (int g = t0 + blockIdx.x; g < tN; g += gridDim.x) {
        int b = bBase;
        while (b < bBase + bCnt - 1 && g >= g_etile[b + 1]) b++;
        const int hfz = b / 21;              // 1 -> hf[src] statically zero
        const int gi = b % 3;
        const int estart = g_eoff[b] + (g - g_etile[b]) * MSG_TE;
        const int ne = min(MSG_TE, g_eoff[b + 1] - estart);
        const float* __restrict__ w1 = w1a + (size_t)gi * H2 * H;
        const float* __restrict__ w2 = w2a + (size_t)gi * H * H;
        const float* __restrict__ w3 = w3a + (size_t)gi * H * H;
        const float* __restrict__ tbl = g_hsl1 + (size_t)gi * 6 * H;

        // ---- stage edge endpoints + src gate type ----
        if (tid < MSG_TE) {
            if (tid < ne) {
                int eid = g_elist[estart + tid];
                int src = ei[eid];
                ssrc[tid] = src;
                sdst[tid] = ei[N_EDGES + eid];
                sgt[tid] = gate[src];
            } else {
                ssrc[tid] = -1;
                sgt[tid] = 0;
            }
        }
        __syncthreads();

        // ---- layer 1 ----
        float acc0[16], acc1[16];
        if (hfz) {
            // pure table lookup, no node-state gather at all
#pragma unroll
            for (int e = 0; e < 16; e++) {
                int gt = sgt[eh * 16 + e];
                acc0[e] = __ldg(&tbl[gt * H + c0]);
                acc1[e] = __ldg(&tbl[gt * H + c0 + 64]);
            }
        } else {
            // gather hf[src] (float4, coalesced per warp)
            for (int p = wrp; p < MSG_TE; p += 4) {
                int src = ssrc[p];
                float4 v = make_float4(0.f, 0.f, 0.f, 0.f);
                if (src >= 0) v = ((const float4*)(hf + (size_t)src * H))[lane];
                hfs4[p][lane] = v;
            }
#pragma unroll
            for (int e = 0; e < 16; e++) {
                int gt = sgt[eh * 16 + e];
                acc0[e] = __ldg(&tbl[gt * H + c0]);
                acc1[e] = __ldg(&tbl[gt * H + c0 + 64]);
            }
            __syncthreads();
            const float* w1b = w1 + (size_t)H * H;   // hf half: rows 128..255
            for (int k4 = 0; k4 < H / 4; k4++) {
                const float* wr = w1b + (k4 * 4) * H;
                float wa0 = wr[c0],         wa1 = wr[H + c0],
                      wa2 = wr[2 * H + c0], wa3 = wr[3 * H + c0];
                float wb0 = wr[c0 + 64],         wb1 = wr[H + c0 + 64],
                      wb2 = wr[2 * H + c0 + 64], wb3 = wr[3 * H + c0 + 64];
#pragma unroll
                for (int e = 0; e < 16; e++) {
                    float4 x = hfs4[eh * 16 + e][k4];
                    acc0[e] = fmaf(x.x, wa0, acc0[e]); acc0[e] = fmaf(x.y, wa1, acc0[e]);
                    acc0[e] = fmaf(x.z, wa2, acc0[e]); acc0[e] = fmaf(x.w, wa3, acc0[e]);
                    acc1[e] = fmaf(x.x, wb0, acc1[e]); acc1[e] = fmaf(x.y, wb1, acc1[e]);
                    acc1[e] = fmaf(x.z, wb2, acc1[e]); acc1[e] = fmaf(x.w, wb3, acc1[e]);
                }
            }
        }
        {
            float bb0 = b1a[gi * H + c0], bb1 = b1a[gi * H + c0 + 64];
            float* h1f = (float*)h14;
#pragma unroll
            for (int e = 0; e < 16; e++) {
                int ge = eh * 16 + e;
                h1f[ge * H + c0]      = fmaxf(acc0[e] + bb0, 0.f);
                h1f[ge * H + c0 + 64] = fmaxf(acc1[e] + bb1, 0.f);
            }
        }
        __syncthreads();

        // ---- layer 2: [32,128] x [128,128] ----
#pragma unroll
        for (int e = 0; e < 16; e++) { acc0[e] = 0.f; acc1[e] = 0.f; }
        for (int k4 = 0; k4 < H / 4; k4++) {
            const float* wr = w2 + (k4 * 4) * H;
            float wa0 = wr[c0],         wa1 = wr[H + c0],
                  wa2 = wr[2 * H + c0], wa3 = wr[3 * H + c0];
            float wb0 = wr[c0 + 64],         wb1 = wr[H + c0 + 64],
                  wb2 = wr[2 * H + c0 + 64], wb3 = wr[3 * H + c0 + 64];
#pragma unroll
            for (int e = 0; e < 16; e++) {
                float4 x = h14[eh * 16 + e][k4];
                acc0[e] = fmaf(x.x, wa0, acc0[e]); acc0[e] = fmaf(x.y, wa1, acc0[e]);
                acc0[e] = fmaf(x.z, wa2, acc0[e]); acc0[e] = fmaf(x.w, wa3, acc0[e]);
                acc1[e] = fmaf(x.x, wb0, acc1[e]); acc1[e] = fmaf(x.y, wb1, acc1[e]);
                acc1[e] = fmaf(x.z, wb2, acc1[e]); acc1[e] = fmaf(x.w, wb3, acc1[e]);
            }
        }
        {
            float bb0 = b2a[gi * H + c0], bb1 = b2a[gi * H + c0 + 64];
            float* h2f = (float*)h24;
#pragma unroll
            for (int e = 0; e < 16; e++) {
                int ge = eh * 16 + e;
                h2f[ge * H + c0]      = fmaxf(acc0[e] + bb0, 0.f);
                h2f[ge * H + c0 + 64] = fmaxf(acc1[e] + bb1, 0.f);
            }
        }
        __syncthreads();

        // ---- layer 3: [32,128] x [128,128] -> scatter-add ----
#pragma unroll
        for (int e = 0; e < 16; e++) { acc0[e] = 0.f; acc1[e] = 0.f; }
        for (int k4 = 0; k4 < H / 4; k4++) {
            const float* wr = w3 + (k4 * 4) * H;
            float wa0 = wr[c0],         wa1 = wr[H + c0],
                  wa2 = wr[2 * H + c0], wa3 = wr[3 * H + c0];
            float wb0 = wr[c0 + 64],         wb1 = wr[H + c0 + 64],
                  wb2 = wr[2 * H + c0 + 64], wb3 = wr[3 * H + c0 + 64];
#pragma unroll
            for (int e = 0; e < 16; e++) {
                float4 x = h24[eh * 16 + e][k4];
                acc0[e] = fmaf(x.x, wa0, acc0[e]); acc0[e] = fmaf(x.y, wa1, acc0[e]);
                acc0[e] = fmaf(x.z, wa2, acc0[e]); acc0[e] = fmaf(x.w, wa3, acc0[e]);
                acc1[e] = fmaf(x.x, wb0, acc1[e]); acc1[e] = fmaf(x.y, wb1, acc1[e]);
                acc1[e] = fmaf(x.z, wb2, acc1[e]); acc1[e] = fmaf(x.w, wb3, acc1[e]);
            }
        }
        {
            float bb0 = b3a[gi * H + c0], bb1 = b3a[gi * H + c0 + 64];
            for (int e = 0; e < 16; e++) {
                int ge = eh * 16 + e;
                if (ge < ne) {
                    int d = sdst[ge];
                    atomicAdd(&g_msg[(size_t)d * H + c0],      acc0[e] + bb0);
                    atomicAdd(&g_msg[(size_t)d * H + c0 + 64], acc1[e] + bb1);
                }
            }
        }
        __syncthreads();
    }
}

// ---------------- fused per-level GRU kernel ------------------------------
// h_old is provably zero (each node updated exactly once): whh GEMM -> bhh bias.
// Block = 128 threads (thread = feature j), tile = 16 nodes.
__global__ void __launch_bounds__(128) k_gru_lvl(
        const float* __restrict__ bih_a, const float* __restrict__ bhh_a,
        float* __restrict__ outbuf, int lvl) {
    __shared__ float4 ms4[GRU_TN][H / 4];    // 8 KB
    __shared__ int snode[GRU_TN];

    const int b0 = (lvl - 1) * 3;
    const int t0 = g_ntile[b0];
    const int t3 = g_ntile[b0 + 3];
    const int tid = threadIdx.x;
    const int lane = tid & 31, wrp = tid >> 5;
    const int j = tid;
    float* hf = outbuf + (size_t)N_NODES * H;

    for (int g = t0 + blockIdx.x; g < t3; g += gridDim.x) {
        int b = b0;
        while (b < b0 + 2 && g >= g_ntile[b + 1]) b++;
        const int gi = b - b0;
        const int nstart = g_noff[b] + (g - g_ntile[b]) * GRU_TN;
        const int nn = min(GRU_TN, g_noff[b + 1] - nstart);
        const float* __restrict__ wihT = g_wihT + (size_t)gi * H * H3;

        if (tid < GRU_TN)
            snode[tid] = (tid < nn) ? g_nlist[nstart + tid] : -1;
        __syncthreads();

        for (int p = wrp; p < GRU_TN; p += 4) {
            int node = snode[p];
            float4 v = make_float4(0.f, 0.f, 0.f, 0.f);
            if (node >= 0) v = ((const float4*)(g_msg + (size_t)node * H))[lane];
            ms4[p][lane] = v;
        }
        __syncthreads();

        float ar[GRU_TN], az[GRU_TN], an[GRU_TN];
#pragma unroll
        for (int e = 0; e < GRU_TN; e++) { ar[e] = 0.f; az[e] = 0.f; an[e] = 0.f; }

        for (int k4 = 0; k4 < H / 4; k4++) {
            const float* wr = wihT + (size_t)(k4 * 4) * H3;
            float r0 = wr[j],            r1 = wr[H3 + j],
                  r2 = wr[2 * H3 + j],   r3 = wr[3 * H3 + j];
            float z0 = wr[H + j],           z1 = wr[H3 + H + j],
                  z2 = wr[2 * H3 + H + j],  z3 = wr[3 * H3 + H + j];
            float n0 = wr[2 * H + j],          n1 = wr[H3 + 2 * H + j],
                  n2 = wr[2 * H3 + 2 * H + j], n3 = wr[3 * H3 + 2 * H + j];
#pragma unroll
            for (int e = 0; e < GRU_TN; e++) {
                float4 m = ms4[e][k4];
                ar[e] = fmaf(m.x, r0, ar[e]); ar[e] = fmaf(m.y, r1, ar[e]);
                ar[e] = fmaf(m.z, r2, ar[e]); ar[e] = fmaf(m.w, r3, ar[e]);
                az[e] = fmaf(m.x, z0, az[e]); az[e] = fmaf(m.y, z1, az[e]);
                az[e] = fmaf(m.z, z2, az[e]); az[e] = fmaf(m.w, z3, az[e]);
                an[e] = fmaf(m.x, n0, an[e]); an[e] = fmaf(m.y, n1, an[e]);
                an[e] = fmaf(m.z, n2, an[e]); an[e] = fmaf(m.w, n3, an[e]);
            }
        }

        const float bir = bih_a[gi * H3 + j]            + bhh_a[gi * H3 + j];
        const float biz = bih_a[gi * H3 + H + j]        + bhh_a[gi * H3 + H + j];
        const float bin_ = bih_a[gi * H3 + 2 * H + j];
        const float bhn  = bhh_a[gi * H3 + 2 * H + j];
        for (int e = 0; e < GRU_TN; e++) {
            int node = snode[e];
            if (node >= 0) {
                float r = 1.0f / (1.0f + expf(-(ar[e] + bir)));
                float z = 1.0f / (1.0f + expf(-(az[e] + biz)));
                float nst = tanhf(an[e] + bin_ + r * bhn);
                hf[(size_t)node * H + j] = (1.0f - z) * nst;
            }
        }
        __syncthreads();
    }
}

// ---------------- launch ---------------------------------------------------

extern "C" void kernel_launch(void* const* d_in, const int* in_sizes, int n_in,
                              void* d_out, int out_size) {
    const int* gate    = (const int*)d_in[0];
    const int* flevel  = (const int*)d_in[1];
    const int* ei      = (const int*)d_in[2];
    const float* Ws    = (const float*)d_in[3];
    const float* Wt    = (const float*)d_in[4];
    const float* hs_W  = (const float*)d_in[5];
    const float* hs_b  = (const float*)d_in[6];
    const float* w1    = (const float*)d_in[7];
    const float* b1    = (const float*)d_in[8];
    const float* w2    = (const float*)d_in[9];
    const float* b2    = (const float*)d_in[10];
    const float* w3    = (const float*)d_in[11];
    const float* b3    = (const float*)d_in[12];
    const float* wih   = (const float*)d_in[13];
    const float* bih   = (const float*)d_in[15];
    const float* bhh   = (const float*)d_in[16];
    float* out = (float*)d_out;

    k_hs_type<<<6, H>>>(Ws, Wt, hs_W, hs_b);
    k_hsl1<<<dim3(3, 6), H>>>(w1);
    k_transpose<<<256, 256>>>(wih);
    k_hs_fill<<<2048, 256>>>((float4*)out, gate);
    k_count<<<1024, 256>>>(ei, gate, flevel);
    k_scan<<<1, 32>>>();
    k_fill_lists<<<1024, 256>>>(ei, gate, flevel);

    // All z=1 (statically-zero-hf) message edges across ALL levels: one
    // full-occupancy launch — they depend only on the gate-type table.
    k_msg_range<<<1184, 128>>>(ei, gate, out, w1, b1, w2, b2, w3, b3, 21, 21);

    for (int lvl = 1; lvl <= 7; lvl++) {
        // z=0 message edges of this level (read hf of earlier levels).
        // Level 1 has none: hf of any src is still zero.
        if (lvl >= 2)
            k_msg_range<<<1184, 128>>>(ei, gate, out, w1, b1, w2, b2, w3, b3,
                                       (lvl - 1) * 3, 3);
        k_gru_lvl<<<1184, 128>>>(bih, bhh, out, lvl);
    }
}

// round 12
// speedup vs baseline: 1.0692x; 1.0692x over previous
#include <cuda_runtime.h>
#include <math.h>

#define N_NODES 100000
#define N_EDGES 200000
#define H 128
#define H2 256
#define H3 384
#define NLVL 7
#define NBUCK_E 42        // z*21 + (l-1)*3 + gi ; z=1 -> hf[src] statically zero
#define NBUCK_N 21        // (l-1)*3 + gi
#define MSG_TE 32         // edges per msg tile
#define GRU_TN 16         // nodes per gru tile

// ---------------- device scratch (static: no allocations allowed) ----------
__device__ float g_msg[(size_t)N_NODES * H];   // scatter-add target
__device__ float g_hs_type[6 * H];             // per-gate-type hs row
__device__ float g_hsl1[3 * 6 * H];            // layer1 hs-half table [gi][gtype][j]
__device__ float g_wihT[3 * H * H3];           // transposed GRU input weights [gi][k][row]
__device__ int g_ecount[NBUCK_E];
__device__ int g_eoff[NBUCK_E + 1];
__device__ int g_ecur[NBUCK_E];
__device__ int g_etile[NBUCK_E + 1];
__device__ int g_ncount[NBUCK_N];
__device__ int g_noff[NBUCK_N + 1];
__device__ int g_ncur[NBUCK_N];
__device__ int g_ntile[NBUCK_N + 1];
__device__ int g_elist[N_EDGES];
__device__ int g_nlist[N_NODES];

__device__ __forceinline__ int gate_gi(int g) {
    // GATE_CODES = (3, 2, 5) -> gi 0, 1, 2
    return (g == 3) ? 0 : (g == 2) ? 1 : (g == 5) ? 2 : -1;
}

// edge bucket: z*21 + (l-1)*3 + gi   (z=1: hf[src] statically zero)
__device__ __forceinline__ int edge_bucket(int src, int dst,
                                           const int* gate, const int* lvl) {
    int gi = gate_gi(gate[dst]);
    int l = lvl[dst];
    if (gi < 0 || l < 1 || l > NLVL) return -1;
    int gs = gate_gi(gate[src]);
    int ls = lvl[src];
    int z = !(gs >= 0 && ls >= 1 && ls < l);
    return z * 21 + (l - 1) * 3 + gi;
}

// ---------------- setup kernels -------------------------------------------

__global__ void k_hs_type(const float* __restrict__ Ws, const float* __restrict__ Wt,
                          const float* __restrict__ hsW, const float* __restrict__ hsb) {
    int g = blockIdx.x;      // 0..5
    int j = threadIdx.x;     // 0..127
    if (g == 0 && j < NBUCK_E) g_ecount[j] = 0;
    if (g == 1 && j < NBUCK_N) g_ncount[j] = 0;
    float acc = hsb[j];
#pragma unroll 4
    for (int k = 0; k < H; k++)
        acc = fmaf(Ws[g * H + k], hsW[k * H + j], acc);
#pragma unroll 4
    for (int k = 0; k < H; k++)
        acc = fmaf(Wt[g * H + k], hsW[(H + k) * H + j], acc);
    g_hs_type[g * H + j] = acc;
}

// layer1 hs-half table: hsl1[gi][g][j] = sum_k hs_type[g][k] * w1[gi][k][j]
__global__ void k_hsl1(const float* __restrict__ w1) {
    int gi = blockIdx.x;     // 0..2
    int g = blockIdx.y;      // 0..5
    int j = threadIdx.x;     // 0..127
    const float* w = w1 + (size_t)gi * H2 * H;
    float acc = 0.f;
#pragma unroll 4
    for (int k = 0; k < H; k++)
        acc = fmaf(g_hs_type[g * H + k], w[k * H + j], acc);
    g_hsl1[(gi * 6 + g) * H + j] = acc;
}

// transpose GRU input weights: wihT[gi][k][r] = wih[gi][r][k]
__global__ void k_transpose(const float* __restrict__ wih) {
    const int total = 3 * H3 * H;
    for (int i = blockIdx.x * blockDim.x + threadIdx.x; i < total; i += gridDim.x * blockDim.x) {
        int gi = i / (H3 * H);
        int rem = i - gi * (H3 * H);
        int r = rem / H;
        int k = rem - r * H;
        g_wihT[gi * H * H3 + k * H3 + r] = wih[i];
    }
}

// write hs to out[0:NH), zero hf region out[NH:2NH), zero msg buffer (float4)
__global__ void k_hs_fill(float4* __restrict__ out4, const int* __restrict__ gate) {
    const int total4 = N_NODES * (H / 4);
    const float4* hs4 = (const float4*)g_hs_type;
    float4* msg4 = (float4*)g_msg;
    const float4 z4 = make_float4(0.f, 0.f, 0.f, 0.f);
    for (int i = blockIdx.x * blockDim.x + threadIdx.x; i < total4; i += gridDim.x * blockDim.x) {
        int node = i >> 5;               // H/4 = 32 float4 per row
        int c = i & 31;
        out4[i] = hs4[gate[node] * 32 + c];
        out4[total4 + i] = z4;
        msg4[i] = z4;
    }
}

// count edges/nodes per bucket
__global__ void k_count(const int* __restrict__ ei, const int* __restrict__ gate,
                        const int* __restrict__ lvl) {
    const int total = N_EDGES + N_NODES;
    for (int i = blockIdx.x * blockDim.x + threadIdx.x; i < total; i += gridDim.x * blockDim.x) {
        if (i < N_EDGES) {
            int b = edge_bucket(ei[i], ei[N_EDGES + i], gate, lvl);
            if (b >= 0) atomicAdd(&g_ecount[b], 1);
        } else {
            int n = i - N_EDGES;
            int gi = gate_gi(gate[n]);
            int l = lvl[n];
            if (gi >= 0 && l >= 1 && l <= NLVL) atomicAdd(&g_ncount[(l - 1) * 3 + gi], 1);
        }
    }
}

__global__ void k_scan() {
    if (threadIdx.x == 0) {
        int s = 0, st = 0;
        for (int b = 0; b < NBUCK_E; b++) {
            g_eoff[b] = s; g_ecur[b] = s; g_etile[b] = st;
            st += (g_ecount[b] + MSG_TE - 1) / MSG_TE;
            s += g_ecount[b];
        }
        g_eoff[NBUCK_E] = s; g_etile[NBUCK_E] = st;
        s = 0; st = 0;
        for (int b = 0; b < NBUCK_N; b++) {
            g_noff[b] = s; g_ncur[b] = s; g_ntile[b] = st;
            st += (g_ncount[b] + GRU_TN - 1) / GRU_TN;
            s += g_ncount[b];
        }
        g_noff[NBUCK_N] = s; g_ntile[NBUCK_N] = st;
    }
}

__global__ void k_fill_lists(const int* __restrict__ ei, const int* __restrict__ gate,
                             const int* __restrict__ lvl) {
    const int total = N_EDGES + N_NODES;
    for (int i = blockIdx.x * blockDim.x + threadIdx.x; i < total; i += gridDim.x * blockDim.x) {
        if (i < N_EDGES) {
            int b = edge_bucket(ei[i], ei[N_EDGES + i], gate, lvl);
            if (b >= 0) {
                int pos = atomicAdd(&g_ecur[b], 1);
                g_elist[pos] = i;
            }
        } else {
            int n = i - N_EDGES;
            int gi = gate_gi(gate[n]);
            int l = lvl[n];
            if (gi >= 0 && l >= 1 && l <= NLVL) {
                int pos = atomicAdd(&g_ncur[(l - 1) * 3 + gi], 1);
                g_nlist[pos] = n;
            }
        }
    }
}

// ======== shared helpers for the MLP layers (register-blocked GEMM) ========

// acc += X[32,128] (shared) x W[128,128], thread owns cols (c0, c0+64) x 16 edges
__device__ __forceinline__ void mlp_gemm128(
        const float4* __restrict__ xs,   // [MSG_TE][H/4] rows
        const float* __restrict__ w, int c0, int eh,
        float* acc0, float* acc1) {
    for (int k4 = 0; k4 < H / 4; k4++) {
        const float* wr = w + (k4 * 4) * H;
        float wa0 = wr[c0],         wa1 = wr[H + c0],
              wa2 = wr[2 * H + c0], wa3 = wr[3 * H + c0];
        float wb0 = wr[c0 + 64],         wb1 = wr[H + c0 + 64],
              wb2 = wr[2 * H + c0 + 64], wb3 = wr[3 * H + c0 + 64];
#pragma unroll
        for (int e = 0; e < 16; e++) {
            float4 x = xs[(eh * 16 + e) * (H / 4) + k4];
            acc0[e] = fmaf(x.x, wa0, acc0[e]); acc0[e] = fmaf(x.y, wa1, acc0[e]);
            acc0[e] = fmaf(x.z, wa2, acc0[e]); acc0[e] = fmaf(x.w, wa3, acc0[e]);
            acc1[e] = fmaf(x.x, wb0, acc1[e]); acc1[e] = fmaf(x.y, wb1, acc1[e]);
            acc1[e] = fmaf(x.z, wb2, acc1[e]); acc1[e] = fmaf(x.w, wb3, acc1[e]);
        }
    }
}

// ---------------- z0 message kernel (bucket range, reads hf) ---------------
__global__ void __launch_bounds__(128) k_msg_range(
        const int* __restrict__ ei, const int* __restrict__ gate,
        const float* __restrict__ outbuf,
        const float* __restrict__ w1a, const float* __restrict__ b1a,
        const float* __restrict__ w2a, const float* __restrict__ b2a,
        const float* __restrict__ w3a, const float* __restrict__ b3a,
        int bBase, int bCnt) {
    __shared__ float4 hfs4[MSG_TE][H / 4];   // 16 KB
    __shared__ float4 h14[MSG_TE][H / 4];    // 16 KB
    __shared__ float4 h24[MSG_TE][H / 4];    // 16 KB
    __shared__ int ssrc[MSG_TE];
    __shared__ int sdst[MSG_TE];
    __shared__ int sgt[MSG_TE];

    const int t0 = g_etile[bBase];
    const int tN = g_etile[bBase + bCnt];
    const int tid = threadIdx.x;
    const int lane = tid & 31, wrp = tid >> 5;
    const int c0 = tid & 63;
    const int eh = tid >> 6;
    const float* hf = outbuf + (size_t)N_NODES * H;

    for (int g = t0 + blockIdx.x; g < tN; g += gridDim.x) {
        int b = bBase;
        while (b < bBase + bCnt - 1 && g >= g_etile[b + 1]) b++;
        const int gi = b % 3;
        const int estart = g_eoff[b] + (g - g_etile[b]) * MSG_TE;
        const int ne = min(MSG_TE, g_eoff[b + 1] - estart);
        const float* __restrict__ w1 = w1a + (size_t)gi * H2 * H;
        const float* __restrict__ w2 = w2a + (size_t)gi * H * H;
        const float* __restrict__ w3 = w3a + (size_t)gi * H * H;
        const float* __restrict__ tbl = g_hsl1 + (size_t)gi * 6 * H;

        if (tid < MSG_TE) {
            if (tid < ne) {
                int eid = g_elist[estart + tid];
                int src = ei[eid];
                ssrc[tid] = src;
                sdst[tid] = ei[N_EDGES + eid];
                sgt[tid] = gate[src];
            } else {
                ssrc[tid] = -1;
                sgt[tid] = 0;
            }
        }
        __syncthreads();

        // gather hf[src]
        for (int p = wrp; p < MSG_TE; p += 4) {
            int src = ssrc[p];
            float4 v = make_float4(0.f, 0.f, 0.f, 0.f);
            if (src >= 0) v = ((const float4*)(hf + (size_t)src * H))[lane];
            hfs4[p][lane] = v;
        }
        float acc0[16], acc1[16];
#pragma unroll
        for (int e = 0; e < 16; e++) {
            int gt = sgt[eh * 16 + e];
            acc0[e] = __ldg(&tbl[gt * H + c0]);
            acc1[e] = __ldg(&tbl[gt * H + c0 + 64]);
        }
        __syncthreads();
        mlp_gemm128(&hfs4[0][0], w1 + (size_t)H * H, c0, eh, acc0, acc1);
        {
            float bb0 = b1a[gi * H + c0], bb1 = b1a[gi * H + c0 + 64];
            float* h1f = (float*)h14;
#pragma unroll
            for (int e = 0; e < 16; e++) {
                int ge = eh * 16 + e;
                h1f[ge * H + c0]      = fmaxf(acc0[e] + bb0, 0.f);
                h1f[ge * H + c0 + 64] = fmaxf(acc1[e] + bb1, 0.f);
            }
        }
        __syncthreads();

#pragma unroll
        for (int e = 0; e < 16; e++) { acc0[e] = 0.f; acc1[e] = 0.f; }
        mlp_gemm128(&h14[0][0], w2, c0, eh, acc0, acc1);
        {
            float bb0 = b2a[gi * H + c0], bb1 = b2a[gi * H + c0 + 64];
            float* h2f = (float*)h24;
#pragma unroll
            for (int e = 0; e < 16; e++) {
                int ge = eh * 16 + e;
                h2f[ge * H + c0]      = fmaxf(acc0[e] + bb0, 0.f);
                h2f[ge * H + c0 + 64] = fmaxf(acc1[e] + bb1, 0.f);
            }
        }
        __syncthreads();

#pragma unroll
        for (int e = 0; e < 16; e++) { acc0[e] = 0.f; acc1[e] = 0.f; }
        mlp_gemm128(&h24[0][0], w3, c0, eh, acc0, acc1);
        {
            float bb0 = b3a[gi * H + c0], bb1 = b3a[gi * H + c0 + 64];
            for (int e = 0; e < 16; e++) {
                int ge = eh * 16 + e;
                if (ge < ne) {
                    int d = sdst[ge];
                    atomicAdd(&g_msg[(size_t)d * H + c0],      acc0[e] + bb0);
                    atomicAdd(&g_msg[(size_t)d * H + c0 + 64], acc1[e] + bb1);
                }
            }
        }
        __syncthreads();
    }
}

// ---------------- heterogeneous level kernel -------------------------------
// One launch per lvl=1..8:
//   msg role: z1 (table-only) message tiles of level lvl     (lvl <= 7)
//   gru role: GRU tiles of level lvl-1                       (lvl >= 2)
// The two roles are data-independent (z1 msgs read no hf and write g_msg of
// level-lvl nodes; GRU reads g_msg / writes hf of level-(lvl-1) nodes).
__global__ void __launch_bounds__(128) k_level(
        const int* __restrict__ ei, const int* __restrict__ gate,
        float* __restrict__ outbuf,
        const float* __restrict__ b1a,
        const float* __restrict__ w2a, const float* __restrict__ b2a,
        const float* __restrict__ w3a, const float* __restrict__ b3a,
        const float* __restrict__ bih_a, const float* __restrict__ bhh_a,
        int lvl) {
    __shared__ float4 sbuf[2 * MSG_TE * (H / 4)];   // 32 KB (msg: h1|h2, gru: ms)
    __shared__ int si[2 * MSG_TE];

    const int tid = threadIdx.x;
    const int lane = tid & 31, wrp = tid >> 5;
    float* hf = outbuf + (size_t)N_NODES * H;

    // msg tile range (z1 buckets of level lvl)
    const int ebB = 21 + (lvl - 1) * 3;
    const int eT0 = (lvl <= NLVL) ? g_etile[ebB] : 0;
    const int eT1 = (lvl <= NLVL) ? g_etile[ebB + 3] : 0;
    const int nMsg = eT1 - eT0;
    // gru tile range (level lvl-1)
    const int nbB = (lvl - 2) * 3;
    const int nT0 = (lvl >= 2) ? g_ntile[nbB] : 0;
    const int nT1 = (lvl >= 2) ? g_ntile[nbB + 3] : 0;
    const int nGru = nT1 - nT0;

    for (int t = blockIdx.x; t < nMsg + nGru; t += gridDim.x) {
        if (t < nMsg) {
            // ================= z1 message tile =================
            const int g = eT0 + t;
            int b = ebB;
            while (b < ebB + 2 && g >= g_etile[b + 1]) b++;
            const int gi = b % 3;
            const int estart = g_eoff[b] + (g - g_etile[b]) * MSG_TE;
            const int ne = min(MSG_TE, g_eoff[b + 1] - estart);
            const float* __restrict__ w2 = w2a + (size_t)gi * H * H;
            const float* __restrict__ w3 = w3a + (size_t)gi * H * H;
            const float* __restrict__ tbl = g_hsl1 + (size_t)gi * 6 * H;
            const int c0 = tid & 63;
            const int eh = tid >> 6;
            float4* h14 = sbuf;
            float4* h24 = sbuf + MSG_TE * (H / 4);
            int* sdst = si;
            int* sgt = si + MSG_TE;

            if (tid < MSG_TE) {
                if (tid < ne) {
                    int eid = g_elist[estart + tid];
                    sdst[tid] = ei[N_EDGES + eid];
                    sgt[tid] = gate[ei[eid]];
                } else {
                    sdst[tid] = -1;
                    sgt[tid] = 0;
                }
            }
            __syncthreads();

            float acc0[16], acc1[16];
            float bb0 = b1a[gi * H + c0], bb1 = b1a[gi * H + c0 + 64];
            {
                float* h1f = (float*)h14;
#pragma unroll
                for (int e = 0; e < 16; e++) {
                    int gt = sgt[eh * 16 + e];
                    h1f[(eh * 16 + e) * H + c0] =
                        fmaxf(__ldg(&tbl[gt * H + c0]) + bb0, 0.f);
                    h1f[(eh * 16 + e) * H + c0 + 64] =
                        fmaxf(__ldg(&tbl[gt * H + c0 + 64]) + bb1, 0.f);
                }
            }
            __syncthreads();

#pragma unroll
            for (int e = 0; e < 16; e++) { acc0[e] = 0.f; acc1[e] = 0.f; }
            mlp_gemm128(h14, w2, c0, eh, acc0, acc1);
            {
                float cb0 = b2a[gi * H + c0], cb1 = b2a[gi * H + c0 + 64];
                float* h2f = (float*)h24;
#pragma unroll
                for (int e = 0; e < 16; e++) {
                    int ge = eh * 16 + e;
                    h2f[ge * H + c0]      = fmaxf(acc0[e] + cb0, 0.f);
                    h2f[ge * H + c0 + 64] = fmaxf(acc1[e] + cb1, 0.f);
                }
            }
            __syncthreads();

#pragma unroll
            for (int e = 0; e < 16; e++) { acc0[e] = 0.f; acc1[e] = 0.f; }
            mlp_gemm128(h24, w3, c0, eh, acc0, acc1);
            {
                float db0 = b3a[gi * H + c0], db1 = b3a[gi * H + c0 + 64];
                for (int e = 0; e < 16; e++) {
                    int ge = eh * 16 + e;
                    if (ge < ne) {
                        int d = sdst[ge];
                        atomicAdd(&g_msg[(size_t)d * H + c0],      acc0[e] + db0);
                        atomicAdd(&g_msg[(size_t)d * H + c0 + 64], acc1[e] + db1);
                    }
                }
            }
            __syncthreads();
        } else {
            // ================= GRU tile (level lvl-1) =================
            const int g = nT0 + (t - nMsg);
            int b = nbB;
            while (b < nbB + 2 && g >= g_ntile[b + 1]) b++;
            const int gi = b - nbB;
            const int nstart = g_noff[b] + (g - g_ntile[b]) * GRU_TN;
            const int nn = min(GRU_TN, g_noff[b + 1] - nstart);
            const float* __restrict__ wihT = g_wihT + (size_t)gi * H * H3;
            const int j = tid;
            float4* ms4 = sbuf;          // GRU_TN * (H/4) = 512 float4
            int* snode = si;

            if (tid < GRU_TN)
                snode[tid] = (tid < nn) ? g_nlist[nstart + tid] : -1;
            __syncthreads();

            for (int p = wrp; p < GRU_TN; p += 4) {
                int node = snode[p];
                float4 v = make_float4(0.f, 0.f, 0.f, 0.f);
                if (node >= 0) v = ((const float4*)(g_msg + (size_t)node * H))[lane];
                ms4[p * (H / 4) + lane] = v;
            }
            __syncthreads();

            float ar[GRU_TN], az[GRU_TN], an[GRU_TN];
#pragma unroll
            for (int e = 0; e < GRU_TN; e++) { ar[e] = 0.f; az[e] = 0.f; an[e] = 0.f; }

            for (int k4 = 0; k4 < H / 4; k4++) {
                const float* wr = wihT + (size_t)(k4 * 4) * H3;
                float r0 = wr[j],            r1 = wr[H3 + j],
                      r2 = wr[2 * H3 + j],   r3 = wr[3 * H3 + j];
                float z0 = wr[H + j],           z1 = wr[H3 + H + j],
                      z2 = wr[2 * H3 + H + j],  z3 = wr[3 * H3 + H + j];
                float n0 = wr[2 * H + j],          n1 = wr[H3 + 2 * H + j],
                      n2 = wr[2 * H3 + 2 * H + j], n3 = wr[3 * H3 + 2 * H + j];
#pragma unroll
                for (int e = 0; e < GRU_TN; e++) {
                    float4 m = ms4[e * (H / 4) + k4];
                    ar[e] = fmaf(m.x, r0, ar[e]); ar[e] = fmaf(m.y, r1, ar[e]);
                    ar[e] = fmaf(m.z, r2, ar[e]); ar[e] = fmaf(m.w, r3, ar[e]);
                    az[e] = fmaf(m.x, z0, az[e]); az[e] = fmaf(m.y, z1, az[e]);
                    az[e] = fmaf(m.z, z2, az[e]); az[e] = fmaf(m.w, z3, az[e]);
                    an[e] = fmaf(m.x, n0, an[e]); an[e] = fmaf(m.y, n1, an[e]);
                    an[e] = fmaf(m.z, n2, an[e]); an[e] = fmaf(m.w, n3, an[e]);
                }
            }

            const float bir = bih_a[gi * H3 + j]     + bhh_a[gi * H3 + j];
            const float biz = bih_a[gi * H3 + H + j] + bhh_a[gi * H3 + H + j];
            const float bin_ = bih_a[gi * H3 + 2 * H + j];
            const float bhn  = bhh_a[gi * H3 + 2 * H + j];
            for (int e = 0; e < GRU_TN; e++) {
                int node = snode[e];
                if (node >= 0) {
                    float r = 1.0f / (1.0f + expf(-(ar[e] + bir)));
                    float z = 1.0f / (1.0f + expf(-(az[e] + biz)));
                    float nst = tanhf(an[e] + bin_ + r * bhn);
                    hf[(size_t)node * H + j] = (1.0f - z) * nst;
                }
            }
            __syncthreads();
        }
    }
}

// ---------------- launch ---------------------------------------------------

extern "C" void kernel_launch(void* const* d_in, const int* in_sizes, int n_in,
                              void* d_out, int out_size) {
    const int* gate    = (const int*)d_in[0];
    const int* flevel  = (const int*)d_in[1];
    const int* ei      = (const int*)d_in[2];
    const float* Ws    = (const float*)d_in[3];
    const float* Wt    = (const float*)d_in[4];
    const float* hs_W  = (const float*)d_in[5];
    const float* hs_b  = (const float*)d_in[6];
    const float* w1    = (const float*)d_in[7];
    const float* b1    = (const float*)d_in[8];
    const float* w2    = (const float*)d_in[9];
    const float* b2    = (const float*)d_in[10];
    const float* w3    = (const float*)d_in[11];
    const float* b3    = (const float*)d_in[12];
    const float* wih   = (const float*)d_in[13];
    const float* bih   = (const float*)d_in[15];
    const float* bhh   = (const float*)d_in[16];
    float* out = (float*)d_out;

    k_hs_type<<<6, H>>>(Ws, Wt, hs_W, hs_b);
    k_hsl1<<<dim3(3, 6), H>>>(w1);
    k_transpose<<<256, 256>>>(wih);
    k_hs_fill<<<2048, 256>>>((float4*)out, gate);
    k_count<<<1024, 256>>>(ei, gate, flevel);
    k_scan<<<1, 32>>>();
    k_fill_lists<<<1024, 256>>>(ei, gate, flevel);

    // A_l: heterogeneous [z1msg(l) || GRU(l-1)]; B_l: z0msg(l).
    // Chain: A_l -> B_l -> A_{l+1} preserves msg(l) < GRU(l) < z0msg(l+1).
    for (int lvl = 1; lvl <= 8; lvl++) {
        k_level<<<1184, 128>>>(ei, gate, out, b1, w2, b2, w3, b3, bih, bhh, lvl);
        if (lvl >= 2 && lvl <= NLVL)
            k_msg_range<<<1184, 128>>>(ei, gate, out, w1, b1, w2, b2, w3, b3,
                                       (lvl - 1) * 3, 3);
    }
}

// round 13
// speedup vs baseline: 1.0790x; 1.0092x over previous
#include <cuda_runtime.h>
#include <math.h>

#define N_NODES 100000
#define N_EDGES 200000
#define H 128
#define H2 256
#define H3 384
#define NLVL 7
#define NBUCK_E 42        // (l-1)*6 + gi*2 + z ; z=1 -> hf[src] statically zero
#define NBUCK_N 21        // (l-1)*3 + gi
#define MSG_TE 32         // edges per msg tile
#define GRU_TN 16         // nodes per gru tile
#define PERSIST_BLOCKS 592   // 4 x 148; <= 4/SM resident on 148+ SMs

// ---------------- device scratch (static: no allocations allowed) ----------
__device__ float g_msg[(size_t)N_NODES * H];   // scatter-add target
__device__ float g_hs_type[6 * H];             // per-gate-type hs row
__device__ float g_hsl1[3 * 6 * H];            // layer1 hs-half table [gi][gtype][j]
__device__ float g_wihT[3 * H * H3];           // transposed GRU input weights [gi][k][row]
__device__ int g_ecount[NBUCK_E];
__device__ int g_eoff[NBUCK_E + 1];
__device__ int g_ecur[NBUCK_E];
__device__ int g_etile[NBUCK_E + 1];
__device__ int g_ncount[NBUCK_N];
__device__ int g_noff[NBUCK_N + 1];
__device__ int g_ncur[NBUCK_N];
__device__ int g_ntile[NBUCK_N + 1];
__device__ int g_elist[N_EDGES];
__device__ int g_nlist[N_NODES];
__device__ unsigned g_arrive;                  // persistent-kernel grid barrier

__device__ __forceinline__ int gate_gi(int g) {
    // GATE_CODES = (3, 2, 5) -> gi 0, 1, 2
    return (g == 3) ? 0 : (g == 2) ? 1 : (g == 5) ? 2 : -1;
}

// edge bucket: (l-1)*6 + gi*2 + z   (z=1: hf[src] statically zero)
__device__ __forceinline__ int edge_bucket(int src, int dst,
                                           const int* gate, const int* lvl) {
    int gi = gate_gi(gate[dst]);
    int l = lvl[dst];
    if (gi < 0 || l < 1 || l > NLVL) return -1;
    int gs = gate_gi(gate[src]);
    int ls = lvl[src];
    int z = !(gs >= 0 && ls >= 1 && ls < l);
    return (l - 1) * 6 + gi * 2 + z;
}

// ---------------- setup kernels -------------------------------------------

__global__ void k_hs_type(const float* __restrict__ Ws, const float* __restrict__ Wt,
                          const float* __restrict__ hsW, const float* __restrict__ hsb) {
    int g = blockIdx.x;      // 0..5
    int j = threadIdx.x;     // 0..127
    if (g == 0 && j < NBUCK_E) g_ecount[j] = 0;
    if (g == 1 && j < NBUCK_N) g_ncount[j] = 0;
    float acc = hsb[j];
#pragma unroll 4
    for (int k = 0; k < H; k++)
        acc = fmaf(Ws[g * H + k], hsW[k * H + j], acc);
#pragma unroll 4
    for (int k = 0; k < H; k++)
        acc = fmaf(Wt[g * H + k], hsW[(H + k) * H + j], acc);
    g_hs_type[g * H + j] = acc;
}

// layer1 hs-half table: hsl1[gi][g][j] = sum_k hs_type[g][k] * w1[gi][k][j]
__global__ void k_hsl1(const float* __restrict__ w1) {
    int gi = blockIdx.x;     // 0..2
    int g = blockIdx.y;      // 0..5
    int j = threadIdx.x;     // 0..127
    const float* w = w1 + (size_t)gi * H2 * H;
    float acc = 0.f;
#pragma unroll 4
    for (int k = 0; k < H; k++)
        acc = fmaf(g_hs_type[g * H + k], w[k * H + j], acc);
    g_hsl1[(gi * 6 + g) * H + j] = acc;
}

// transpose GRU input weights: wihT[gi][k][r] = wih[gi][r][k]
__global__ void k_transpose(const float* __restrict__ wih) {
    const int total = 3 * H3 * H;
    for (int i = blockIdx.x * blockDim.x + threadIdx.x; i < total; i += gridDim.x * blockDim.x) {
        int gi = i / (H3 * H);
        int rem = i - gi * (H3 * H);
        int r = rem / H;
        int k = rem - r * H;
        g_wihT[gi * H * H3 + k * H3 + r] = wih[i];
    }
}

// write hs to out[0:NH), zero hf region out[NH:2NH), zero msg buffer (float4)
__global__ void k_hs_fill(float4* __restrict__ out4, const int* __restrict__ gate) {
    const int total4 = N_NODES * (H / 4);
    const float4* hs4 = (const float4*)g_hs_type;
    float4* msg4 = (float4*)g_msg;
    const float4 z4 = make_float4(0.f, 0.f, 0.f, 0.f);
    for (int i = blockIdx.x * blockDim.x + threadIdx.x; i < total4; i += gridDim.x * blockDim.x) {
        int node = i >> 5;               // H/4 = 32 float4 per row
        int c = i & 31;
        out4[i] = hs4[gate[node] * 32 + c];
        out4[total4 + i] = z4;
        msg4[i] = z4;
    }
}

// count edges/nodes per bucket
__global__ void k_count(const int* __restrict__ ei, const int* __restrict__ gate,
                        const int* __restrict__ lvl) {
    const int total = N_EDGES + N_NODES;
    for (int i = blockIdx.x * blockDim.x + threadIdx.x; i < total; i += gridDim.x * blockDim.x) {
        if (i < N_EDGES) {
            int b = edge_bucket(ei[i], ei[N_EDGES + i], gate, lvl);
            if (b >= 0) atomicAdd(&g_ecount[b], 1);
        } else {
            int n = i - N_EDGES;
            int gi = gate_gi(gate[n]);
            int l = lvl[n];
            if (gi >= 0 && l >= 1 && l <= NLVL) atomicAdd(&g_ncount[(l - 1) * 3 + gi], 1);
        }
    }
}

__global__ void k_scan() {
    if (threadIdx.x == 0) {
        g_arrive = 0u;                    // reset persistent-kernel barrier
        int s = 0, st = 0;
        for (int b = 0; b < NBUCK_E; b++) {
            g_eoff[b] = s; g_ecur[b] = s; g_etile[b] = st;
            st += (g_ecount[b] + MSG_TE - 1) / MSG_TE;
            s += g_ecount[b];
        }
        g_eoff[NBUCK_E] = s; g_etile[NBUCK_E] = st;
        s = 0; st = 0;
        for (int b = 0; b < NBUCK_N; b++) {
            g_noff[b] = s; g_ncur[b] = s; g_ntile[b] = st;
            st += (g_ncount[b] + GRU_TN - 1) / GRU_TN;
            s += g_ncount[b];
        }
        g_noff[NBUCK_N] = s; g_ntile[NBUCK_N] = st;
    }
}

__global__ void k_fill_lists(const int* __restrict__ ei, const int* __restrict__ gate,
                             const int* __restrict__ lvl) {
    const int total = N_EDGES + N_NODES;
    for (int i = blockIdx.x * blockDim.x + threadIdx.x; i < total; i += gridDim.x * blockDim.x) {
        if (i < N_EDGES) {
            int b = edge_bucket(ei[i], ei[N_EDGES + i], gate, lvl);
            if (b >= 0) {
                int pos = atomicAdd(&g_ecur[b], 1);
                g_elist[pos] = i;
            }
        } else {
            int n = i - N_EDGES;
            int gi = gate_gi(gate[n]);
            int l = lvl[n];
            if (gi >= 0 && l >= 1 && l <= NLVL) {
                int pos = atomicAdd(&g_ncur[(l - 1) * 3 + gi], 1);
                g_nlist[pos] = n;
            }
        }
    }
}

// ---------------- persistent level kernel ----------------------------------
// All 592 blocks are co-resident (4/SM by smem and __launch_bounds__), so a
// software grid barrier is safe. Executes R8's proven schedule internally:
//   for lvl 1..7: msg(lvl) [z1+z0 buckets]  <barrier>  gru(lvl)  <barrier>
// Monotonic-counter barrier (reset in k_scan each launch) avoids generation
// races; __threadfence orders g_msg / hf writes across phases.

__device__ __forceinline__ void grid_sync(unsigned target) {
    __syncthreads();
    if (threadIdx.x == 0) {
        __threadfence();
        atomicAdd(&g_arrive, 1u);
        while (atomicAdd(&g_arrive, 0u) < target) { }
        __threadfence();
    }
    __syncthreads();
}

__global__ void __launch_bounds__(128, 4) k_run(
        const int* __restrict__ ei, const int* __restrict__ gate,
        float* __restrict__ outbuf,
        const float* __restrict__ w1a, const float* __restrict__ b1a,
        const float* __restrict__ w2a, const float* __restrict__ b2a,
        const float* __restrict__ w3a, const float* __restrict__ b3a,
        const float* __restrict__ bih_a, const float* __restrict__ bhh_a) {
    __shared__ float4 hfs4[MSG_TE][H / 4];   // 16 KB (gru: ms4 alias)
    __shared__ float4 h14[MSG_TE][H / 4];    // 16 KB
    __shared__ float4 h24[MSG_TE][H / 4];    // 16 KB
    __shared__ int ssrc[MSG_TE];             // gru: snode alias
    __shared__ int sdst[MSG_TE];
    __shared__ int sgt[MSG_TE];

    const int tid = threadIdx.x;
    const int lane = tid & 31, wrp = tid >> 5;
    const int c0 = tid & 63;                 // msg: cols c0, c0+64
    const int eh = tid >> 6;                 // msg: edge half 0/1
    float* hf = outbuf + (size_t)N_NODES * H;
    const int NB = (int)gridDim.x;
    unsigned bar = 0;

    for (int lvl = 1; lvl <= NLVL; lvl++) {
        // ================= message phase: buckets (lvl-1)*6 .. +6 ==========
        {
            const int bBase = (lvl - 1) * 6;
            const int t0 = g_etile[bBase];
            const int tN = g_etile[bBase + 6];
            for (int g = t0 + blockIdx.x; g < tN; g += NB) {
                int b = bBase;
                while (b < bBase + 5 && g >= g_etile[b + 1]) b++;
                const int sub = b - bBase;
                const int gi = sub >> 1;
                const int hfz = sub & 1;         // 1 -> hf[src] statically zero
                const int estart = g_eoff[b] + (g - g_etile[b]) * MSG_TE;
                const int ne = min(MSG_TE, g_eoff[b + 1] - estart);
                const float* __restrict__ w1 = w1a + (size_t)gi * H2 * H;
                const float* __restrict__ w2 = w2a + (size_t)gi * H * H;
                const float* __restrict__ w3 = w3a + (size_t)gi * H * H;
                const float* __restrict__ tbl = g_hsl1 + (size_t)gi * 6 * H;

                if (tid < MSG_TE) {
                    if (tid < ne) {
                        int eid = g_elist[estart + tid];
                        int src = ei[eid];
                        ssrc[tid] = src;
                        sdst[tid] = ei[N_EDGES + eid];
                        sgt[tid] = gate[src];
                    } else {
                        ssrc[tid] = -1;
                        sgt[tid] = 0;
                    }
                }
                __syncthreads();

                // ---- layer 1 ----
                float acc0[16], acc1[16];
                if (hfz) {
#pragma unroll
                    for (int e = 0; e < 16; e++) {
                        int gt = sgt[eh * 16 + e];
                        acc0[e] = __ldg(&tbl[gt * H + c0]);
                        acc1[e] = __ldg(&tbl[gt * H + c0 + 64]);
                    }
                } else {
                    for (int p = wrp; p < MSG_TE; p += 4) {
                        int src = ssrc[p];
                        float4 v = make_float4(0.f, 0.f, 0.f, 0.f);
                        if (src >= 0) v = ((const float4*)(hf + (size_t)src * H))[lane];
                        hfs4[p][lane] = v;
                    }
#pragma unroll
                    for (int e = 0; e < 16; e++) {
                        int gt = sgt[eh * 16 + e];
                        acc0[e] = __ldg(&tbl[gt * H + c0]);
                        acc1[e] = __ldg(&tbl[gt * H + c0 + 64]);
                    }
                    __syncthreads();
                    const float* w1b = w1 + (size_t)H * H;   // hf half rows
                    for (int k4 = 0; k4 < H / 4; k4++) {
                        const float* wr = w1b + (k4 * 4) * H;
                        float wa0 = wr[c0],         wa1 = wr[H + c0],
                              wa2 = wr[2 * H + c0], wa3 = wr[3 * H + c0];
                        float wb0 = wr[c0 + 64],         wb1 = wr[H + c0 + 64],
                              wb2 = wr[2 * H + c0 + 64], wb3 = wr[3 * H + c0 + 64];
#pragma unroll
                        for (int e = 0; e < 16; e++) {
                            float4 x = hfs4[eh * 16 + e][k4];
                            acc0[e] = fmaf(x.x, wa0, acc0[e]); acc0[e] = fmaf(x.y, wa1, acc0[e]);
                            acc0[e] = fmaf(x.z, wa2, acc0[e]); acc0[e] = fmaf(x.w, wa3, acc0[e]);
                            acc1[e] = fmaf(x.x, wb0, acc1[e]); acc1[e] = fmaf(x.y, wb1, acc1[e]);
                            acc1[e] = fmaf(x.z, wb2, acc1[e]); acc1[e] = fmaf(x.w, wb3, acc1[e]);
                        }
                    }
                }
                {
                    float bb0 = b1a[gi * H + c0], bb1 = b1a[gi * H + c0 + 64];
                    float* h1f = (float*)h14;
#pragma unroll
                    for (int e = 0; e < 16; e++) {
                        int ge = eh * 16 + e;
                        h1f[ge * H + c0]      = fmaxf(acc0[e] + bb0, 0.f);
                        h1f[ge * H + c0 + 64] = fmaxf(acc1[e] + bb1, 0.f);
                    }
                }
                __syncthreads();

                // ---- layer 2 ----
#pragma unroll
                for (int e = 0; e < 16; e++) { acc0[e] = 0.f; acc1[e] = 0.f; }
                for (int k4 = 0; k4 < H / 4; k4++) {
                    const float* wr = w2 + (k4 * 4) * H;
                    float wa0 = wr[c0],         wa1 = wr[H + c0],
                          wa2 = wr[2 * H + c0], wa3 = wr[3 * H + c0];
                    float wb0 = wr[c0 + 64],         wb1 = wr[H + c0 + 64],
                          wb2 = wr[2 * H + c0 + 64], wb3 = wr[3 * H + c0 + 64];
#pragma unroll
                    for (int e = 0; e < 16; e++) {
                        float4 x = h14[eh * 16 + e][k4];
                        acc0[e] = fmaf(x.x, wa0, acc0[e]); acc0[e] = fmaf(x.y, wa1, acc0[e]);
                        acc0[e] = fmaf(x.z, wa2, acc0[e]); acc0[e] = fmaf(x.w, wa3, acc0[e]);
                        acc1[e] = fmaf(x.x, wb0, acc1[e]); acc1[e] = fmaf(x.y, wb1, acc1[e]);
                        acc1[e] = fmaf(x.z, wb2, acc1[e]); acc1[e] = fmaf(x.w, wb3, acc1[e]);
                    }
                }
                {
                    float bb0 = b2a[gi * H + c0], bb1 = b2a[gi * H + c0 + 64];
                    float* h2f = (float*)h24;
#pragma unroll
                    for (int e = 0; e < 16; e++) {
                        int ge = eh * 16 + e;
                        h2f[ge * H + c0]      = fmaxf(acc0[e] + bb0, 0.f);
                        h2f[ge * H + c0 + 64] = fmaxf(acc1[e] + bb1, 0.f);
                    }
                }
                __syncthreads();

                // ---- layer 3 -> scatter ----
#pragma unroll
                for (int e = 0; e < 16; e++) { acc0[e] = 0.f; acc1[e] = 0.f; }
                for (int k4 = 0; k4 < H / 4; k4++) {
                    const float* wr = w3 + (k4 * 4) * H;
                    float wa0 = wr[c0],         wa1 = wr[H + c0],
                          wa2 = wr[2 * H + c0], wa3 = wr[3 * H + c0];
                    float wb0 = wr[c0 + 64],         wb1 = wr[H + c0 + 64],
                          wb2 = wr[2 * H + c0 + 64], wb3 = wr[3 * H + c0 + 64];
#pragma unroll
                    for (int e = 0; e < 16; e++) {
                        float4 x = h24[eh * 16 + e][k4];
                        acc0[e] = fmaf(x.x, wa0, acc0[e]); acc0[e] = fmaf(x.y, wa1, acc0[e]);
                        acc0[e] = fmaf(x.z, wa2, acc0[e]); acc0[e] = fmaf(x.w, wa3, acc0[e]);
                        acc1[e] = fmaf(x.x, wb0, acc1[e]); acc1[e] = fmaf(x.y, wb1, acc1[e]);
                        acc1[e] = fmaf(x.z, wb2, acc1[e]); acc1[e] = fmaf(x.w, wb3, acc1[e]);
                    }
                }
                {
                    float bb0 = b3a[gi * H + c0], bb1 = b3a[gi * H + c0 + 64];
                    for (int e = 0; e < 16; e++) {
                        int ge = eh * 16 + e;
                        if (ge < ne) {
                            int d = sdst[ge];
                            atomicAdd(&g_msg[(size_t)d * H + c0],      acc0[e] + bb0);
                            atomicAdd(&g_msg[(size_t)d * H + c0 + 64], acc1[e] + bb1);
                        }
                    }
                }
                __syncthreads();
            }
        }
        bar += PERSIST_BLOCKS;
        grid_sync(bar);

        // ================= GRU phase: level lvl ============================
        {
            const int b0 = (lvl - 1) * 3;
            const int t0 = g_ntile[b0];
            const int t3 = g_ntile[b0 + 3];
            float4 (*ms4)[H / 4] = hfs4;     // alias
            int* snode = ssrc;               // alias
            const int j = tid;

            for (int g = t0 + blockIdx.x; g < t3; g += NB) {
                int b = b0;
                while (b < b0 + 2 && g >= g_ntile[b + 1]) b++;
                const int gi = b - b0;
                const int nstart = g_noff[b] + (g - g_ntile[b]) * GRU_TN;
                const int nn = min(GRU_TN, g_noff[b + 1] - nstart);
                const float* __restrict__ wihT = g_wihT + (size_t)gi * H * H3;

                if (tid < GRU_TN)
                    snode[tid] = (tid < nn) ? g_nlist[nstart + tid] : -1;
                __syncthreads();

                for (int p = wrp; p < GRU_TN; p += 4) {
                    int node = snode[p];
                    float4 v = make_float4(0.f, 0.f, 0.f, 0.f);
                    if (node >= 0) v = ((const float4*)(g_msg + (size_t)node * H))[lane];
                    ms4[p][lane] = v;
                }
                __syncthreads();

                float ar[GRU_TN], az[GRU_TN], an[GRU_TN];
#pragma unroll
                for (int e = 0; e < GRU_TN; e++) { ar[e] = 0.f; az[e] = 0.f; an[e] = 0.f; }

                for (int k4 = 0; k4 < H / 4; k4++) {
                    const float* wr = wihT + (size_t)(k4 * 4) * H3;
                    float r0 = wr[j],            r1 = wr[H3 + j],
                          r2 = wr[2 * H3 + j],   r3 = wr[3 * H3 + j];
                    float z0 = wr[H + j],           z1 = wr[H3 + H + j],
                          z2 = wr[2 * H3 + H + j],  z3 = wr[3 * H3 + H + j];
                    float n0 = wr[2 * H + j],          n1 = wr[H3 + 2 * H + j],
                          n2 = wr[2 * H3 + 2 * H + j], n3 = wr[3 * H3 + 2 * H + j];
#pragma unroll
                    for (int e = 0; e < GRU_TN; e++) {
                        float4 m = ms4[e][k4];
                        ar[e] = fmaf(m.x, r0, ar[e]); ar[e] = fmaf(m.y, r1, ar[e]);
                        ar[e] = fmaf(m.z, r2, ar[e]); ar[e] = fmaf(m.w, r3, ar[e]);
                        az[e] = fmaf(m.x, z0, az[e]); az[e] = fmaf(m.y, z1, az[e]);
                        az[e] = fmaf(m.z, z2, az[e]); az[e] = fmaf(m.w, z3, az[e]);
                        an[e] = fmaf(m.x, n0, an[e]); an[e] = fmaf(m.y, n1, an[e]);
                        an[e] = fmaf(m.z, n2, an[e]); an[e] = fmaf(m.w, n3, an[e]);
                    }
                }

                const float bir = bih_a[gi * H3 + j]     + bhh_a[gi * H3 + j];
                const float biz = bih_a[gi * H3 + H + j] + bhh_a[gi * H3 + H + j];
                const float bin_ = bih_a[gi * H3 + 2 * H + j];
                const float bhn  = bhh_a[gi * H3 + 2 * H + j];
                for (int e = 0; e < GRU_TN; e++) {
                    int node = snode[e];
                    if (node >= 0) {
                        float r = 1.0f / (1.0f + expf(-(ar[e] + bir)));
                        float z = 1.0f / (1.0f + expf(-(az[e] + biz)));
                        float nst = tanhf(an[e] + bin_ + r * bhn);
                        hf[(size_t)node * H + j] = (1.0f - z) * nst;
                    }
                }
                __syncthreads();
            }
        }
        if (lvl < NLVL) {
            bar += PERSIST_BLOCKS;
            grid_sync(bar);
        }
    }
}

// ---------------- launch ---------------------------------------------------

extern "C" void kernel_launch(void* const* d_in, const int* in_sizes, int n_in,
                              void* d_out, int out_size) {
    const int* gate    = (const int*)d_in[0];
    const int* flevel  = (const int*)d_in[1];
    const int* ei      = (const int*)d_in[2];
    const float* Ws    = (const float*)d_in[3];
    const float* Wt    = (const float*)d_in[4];
    const float* hs_W  = (const float*)d_in[5];
    const float* hs_b  = (const float*)d_in[6];
    const float* w1    = (const float*)d_in[7];
    const float* b1    = (const float*)d_in[8];
    const float* w2    = (const float*)d_in[9];
    const float* b2    = (const float*)d_in[10];
    const float* w3    = (const float*)d_in[11];
    const float* b3    = (const float*)d_in[12];
    const float* wih   = (const float*)d_in[13];
    const float* bih   = (const float*)d_in[15];
    const float* bhh   = (const float*)d_in[16];
    float* out = (float*)d_out;

    k_hs_type<<<6, H>>>(Ws, Wt, hs_W, hs_b);
    k_hsl1<<<dim3(3, 6), H>>>(w1);
    k_transpose<<<256, 256>>>(wih);
    k_hs_fill<<<2048, 256>>>((float4*)out, gate);
    k_count<<<1024, 256>>>(ei, gate, flevel);
    k_scan<<<1, 32>>>();
    k_fill_lists<<<1024, 256>>>(ei, gate, flevel);

    // One persistent kernel runs the full 7-level msg/gru schedule with
    // software grid barriers (all 592 blocks co-resident: 4/SM by smem
    // and __launch_bounds__(128, 4)).
    k_run<<<PERSIST_BLOCKS, 128>>>(ei, gate, out, w1, b1, w2, b2, w3, b3,
                                   bih, bhh);
}

// round 15
// speedup vs baseline: 1.1163x; 1.0346x over previous
#include <cuda_runtime.h>
#include <math.h>

#define N_NODES 100000
#define N_EDGES 200000
#define H 128
#define H2 256
#define H3 384
#define NLVL 7
#define NBUCK_E 42        // (l-1)*6 + gi*2 + z ; z=1 -> hf[src] statically zero
#define NBUCK_N 21        // (l-1)*3 + gi
#define NCNT (NBUCK_E + NBUCK_N)
#define MSG_TE 32         // edges per msg tile
#define GRU_TN 16         // nodes per gru tile

// ---------------- device scratch (static: no allocations allowed) ----------
__device__ float g_msg[(size_t)N_NODES * H];   // scatter-add target
__device__ float g_hs_type[6 * H];             // per-gate-type hs row
__device__ float g_hsl1[3 * 6 * H];            // layer1 hs-half table [gi][gtype][j]
__device__ float g_wihT[3 * H * H3];           // transposed GRU input weights [gi][k][row]
__device__ int g_cnt[NCNT];                    // bucket counts; zero at load AND re-zeroed
                                               // by k_setup2 each launch (after scan reads)
__device__ int g_eoff[NBUCK_E + 1];
__device__ int g_ecur[NBUCK_E];
__device__ int g_etile[NBUCK_E + 1];
__device__ int g_noff[NBUCK_N + 1];
__device__ int g_ncur[NBUCK_N];
__device__ int g_ntile[NBUCK_N + 1];
__device__ int g_elist[N_EDGES];
__device__ int g_nlist[N_NODES];

__device__ __forceinline__ int gate_gi(int g) {
    // GATE_CODES = (3, 2, 5) -> gi 0, 1, 2
    return (g == 3) ? 0 : (g == 2) ? 1 : (g == 5) ? 2 : -1;
}

// edge bucket: (l-1)*6 + gi*2 + z   (z=1: hf[src] statically zero)
__device__ __forceinline__ int edge_bucket(int src, int dst,
                                           const int* gate, const int* lvl) {
    int gi = gate_gi(gate[dst]);
    int l = lvl[dst];
    if (gi < 0 || l < 1 || l > NLVL) return -1;
    int gs = gate_gi(gate[src]);
    int ls = lvl[src];
    int z = !(gs >= 0 && ls >= 1 && ls < l);
    return (l - 1) * 6 + gi * 2 + z;
}

// ---------------- K0: hs_type + wih transpose + bucket count --------------
// blocks [0,6): hs_type row for gate type g = blockIdx.x
// blocks [6, grid): grid-stride over [transpose items | count items]
__global__ void k_setup0(const float* __restrict__ Ws, const float* __restrict__ Wt,
                         const float* __restrict__ hsW, const float* __restrict__ hsb,
                         const float* __restrict__ wih,
                         const int* __restrict__ ei, const int* __restrict__ gate,
                         const int* __restrict__ lvl) {
    if (blockIdx.x < 6) {
        int g = blockIdx.x;
        int j = threadIdx.x;
        if (j < H) {
            float acc = hsb[j];
#pragma unroll 4
            for (int k = 0; k < H; k++)
                acc = fmaf(Ws[g * H + k], hsW[k * H + j], acc);
#pragma unroll 4
            for (int k = 0; k < H; k++)
                acc = fmaf(Wt[g * H + k], hsW[(H + k) * H + j], acc);
            g_hs_type[g * H + j] = acc;
        }
        return;
    }
    const int TT = 3 * H3 * H;                 // transpose items
    const int total = TT + N_EDGES + N_NODES;  // + count items
    const int stride = (gridDim.x - 6) * blockDim.x;
    for (int i = (blockIdx.x - 6) * blockDim.x + threadIdx.x; i < total; i += stride) {
        if (i < TT) {
            int gi = i / (H3 * H);
            int rem = i - gi * (H3 * H);
            int r = rem / H;
            int k = rem - r * H;
            g_wihT[gi * H * H3 + k * H3 + r] = wih[i];
        } else {
            int w = i - TT;
            if (w < N_EDGES) {
                int b = edge_bucket(ei[w], ei[N_EDGES + w], gate, lvl);
                if (b >= 0) atomicAdd(&g_cnt[b], 1);
            } else {
                int n = w - N_EDGES;
                int gi = gate_gi(gate[n]);
                int l = lvl[n];
                if (gi >= 0 && l >= 1 && l <= NLVL)
                    atomicAdd(&g_cnt[NBUCK_E + (l - 1) * 3 + gi], 1);
            }
        }
    }
}

// ---------------- K1: hsl1 table + scan ------------------------------------
// 18 blocks: (gi, g) = (blockIdx/6, blockIdx%6); block 0 thread 0 also scans.
__global__ void k_setup1(const float* __restrict__ w1) {
    int gi = blockIdx.x / 6;
    int g = blockIdx.x % 6;
    int j = threadIdx.x;
    const float* w = w1 + (size_t)gi * H2 * H;
    float acc = 0.f;
#pragma unroll 4
    for (int k = 0; k < H; k++)
        acc = fmaf(g_hs_type[g * H + k], w[k * H + j], acc);
    g_hsl1[(gi * 6 + g) * H + j] = acc;

    if (blockIdx.x == 0 && j == 0) {
        int s = 0, st = 0;
        for (int b = 0; b < NBUCK_E; b++) {
            g_eoff[b] = s; g_ecur[b] = s; g_etile[b] = st;
            st += (g_cnt[b] + MSG_TE - 1) / MSG_TE;
            s += g_cnt[b];
        }
        g_eoff[NBUCK_E] = s; g_etile[NBUCK_E] = st;
        s = 0; st = 0;
        for (int b = 0; b < NBUCK_N; b++) {
            g_noff[b] = s; g_ncur[b] = s; g_ntile[b] = st;
            st += (g_cnt[NBUCK_E + b] + GRU_TN - 1) / GRU_TN;
            s += g_cnt[NBUCK_E + b];
        }
        g_noff[NBUCK_N] = s; g_ntile[NBUCK_N] = st;
    }
}

// ---------------- K2: hs_fill + fill_lists + counter re-zero ---------------
__global__ void k_setup2(float4* __restrict__ out4, const int* __restrict__ gate,
                         const int* __restrict__ ei, const int* __restrict__ lvl) {
    // re-zero counters for the NEXT launch (scan already consumed them in K1)
    if (blockIdx.x == 0 && threadIdx.x < NCNT) g_cnt[threadIdx.x] = 0;

    const int F4 = N_NODES * (H / 4);
    const int total = F4 + N_EDGES + N_NODES;
    const float4* hs4 = (const float4*)g_hs_type;
    float4* msg4 = (float4*)g_msg;
    const float4 z4 = make_float4(0.f, 0.f, 0.f, 0.f);
    for (int i = blockIdx.x * blockDim.x + threadIdx.x; i < total; i += gridDim.x * blockDim.x) {
        if (i < F4) {
            int node = i >> 5;
            int c = i & 31;
            out4[i] = hs4[gate[node] * 32 + c];
            out4[F4 + i] = z4;
            msg4[i] = z4;
        } else {
            int w = i - F4;
            if (w < N_EDGES) {
                int b = edge_bucket(ei[w], ei[N_EDGES + w], gate, lvl);
                if (b >= 0) {
                    int pos = atomicAdd(&g_ecur[b], 1);
                    g_elist[pos] = w;
                }
            } else {
                int n = w - N_EDGES;
                int gi = gate_gi(gate[n]);
                int l = lvl[n];
                if (gi >= 0 && l >= 1 && l <= NLVL) {
                    int pos = atomicAdd(&g_ncur[(l - 1) * 3 + gi], 1);
                    g_nlist[pos] = n;
                }
            }
        }
    }
}

// ---------------- per-level message kernel (R8-proven) ---------------------
// Processes edge buckets [bBase, bBase+bCnt). Block = 128 threads, tile = 32
// edges; thread owns cols (c0, c0+64) x 16 edges.
// layer1 = hsl1[gate[src]] (+ hf[src] @ w1[128:256] if z==0) + b1.
__global__ void __launch_bounds__(128) k_msg_range(
        const int* __restrict__ ei, const int* __restrict__ gate,
        const float* __restrict__ outbuf,
        const float* __restrict__ w1a, const float* __restrict__ b1a,
        const float* __restrict__ w2a, const float* __restrict__ b2a,
        const float* __restrict__ w3a, const float* __restrict__ b3a,
        int bBase, int bCnt) {
    __shared__ float4 hfs4[MSG_TE][H / 4];   // 16 KB: hf[src] stage (z==0 only)
    __shared__ float4 h14[MSG_TE][H / 4];    // 16 KB
    __shared__ float4 h24[MSG_TE][H / 4];    // 16 KB
    __shared__ int ssrc[MSG_TE];
    __shared__ int sdst[MSG_TE];
    __shared__ int sgt[MSG_TE];

    const int t0 = g_etile[bBase];
    const int tN = g_etile[bBase + bCnt];
    const int tid = threadIdx.x;
    const int lane = tid & 31, wrp = tid >> 5;
    const int c0 = tid & 63;
    const int eh = tid >> 6;
    const float* hf = outbuf + (size_t)N_NODES * H;

    for (int g = t0 + blockIdx.x; g < tN; g += gridDim.x) {
        int b = bBase;
        while (b < bBase + bCnt - 1 && g >= g_etile[b + 1]) b++;
        const int sub = b - bBase;
        const int gi = sub >> 1;
        const int hfz = sub & 1;             // 1 -> hf[src] statically zero
        const int estart = g_eoff[b] + (g - g_etile[b]) * MSG_TE;
        const int ne = min(MSG_TE, g_eoff[b + 1] - estart);
        const float* __restrict__ w1 = w1a + (size_t)gi * H2 * H;
        const float* __restrict__ w2 = w2a + (size_t)gi * H * H;
        const float* __restrict__ w3 = w3a + (size_t)gi * H * H;
        const float* __restrict__ tbl = g_hsl1 + (size_t)gi * 6 * H;

        if (tid < MSG_TE) {
            if (tid < ne) {
                int eid = g_elist[estart + tid];
                int src = ei[eid];
                ssrc[tid] = src;
                sdst[tid] = ei[N_EDGES + eid];
                sgt[tid] = gate[src];
            } else {
                ssrc[tid] = -1;
                sgt[tid] = 0;
            }
        }
        __syncthreads();

        // ---- layer 1 ----
        float acc0[16], acc1[16];
        if (hfz) {
#pragma unroll
            for (int e = 0; e < 16; e++) {
                int gt = sgt[eh * 16 + e];
                acc0[e] = __ldg(&tbl[gt * H + c0]);
                acc1[e] = __ldg(&tbl[gt * H + c0 + 64]);
            }
        } else {
            for (int p = wrp; p < MSG_TE; p += 4) {
                int src = ssrc[p];
                float4 v = make_float4(0.f, 0.f, 0.f, 0.f);
                if (src >= 0) v = ((const float4*)(hf + (size_t)src * H))[lane];
                hfs4[p][lane] = v;
            }
#pragma unroll
            for (int e = 0; e < 16; e++) {
                int gt = sgt[eh * 16 + e];
                acc0[e] = __ldg(&tbl[gt * H + c0]);
                acc1[e] = __ldg(&tbl[gt * H + c0 + 64]);
            }
            __syncthreads();
            const float* w1b = w1 + (size_t)H * H;   // hf half: rows 128..255
            for (int k4 = 0; k4 < H / 4; k4++) {
                const float* wr = w1b + (k4 * 4) * H;
                float wa0 = wr[c0],         wa1 = wr[H + c0],
                      wa2 = wr[2 * H + c0], wa3 = wr[3 * H + c0];
                float wb0 = wr[c0 + 64],         wb1 = wr[H + c0 + 64],
                      wb2 = wr[2 * H + c0 + 64], wb3 = wr[3 * H + c0 + 64];
#pragma unroll
                for (int e = 0; e < 16; e++) {
                    float4 x = hfs4[eh * 16 + e][k4];
                    acc0[e] = fmaf(x.x, wa0, acc0[e]); acc0[e] = fmaf(x.y, wa1, acc0[e]);
                    acc0[e] = fmaf(x.z, wa2, acc0[e]); acc0[e] = fmaf(x.w, wa3, acc0[e]);
                    acc1[e] = fmaf(x.x, wb0, acc1[e]); acc1[e] = fmaf(x.y, wb1, acc1[e]);
                    acc1[e] = fmaf(x.z, wb2, acc1[e]); acc1[e] = fmaf(x.w, wb3, acc1[e]);
                }
            }
        }
        {
            float bb0 = b1a[gi * H + c0], bb1 = b1a[gi * H + c0 + 64];
            float* h1f = (float*)h14;
#pragma unroll
            for (int e = 0; e < 16; e++) {
                int ge = eh * 16 + e;
                h1f[ge * H + c0]      = fmaxf(acc0[e] + bb0, 0.f);
                h1f[ge * H + c0 + 64] = fmaxf(acc1[e] + bb1, 0.f);
            }
        }
        __syncthreads();

        // ---- layer 2 ----
#pragma unroll
        for (int e = 0; e < 16; e++) { acc0[e] = 0.f; acc1[e] = 0.f; }
        for (int k4 = 0; k4 < H / 4; k4++) {
            const float* wr = w2 + (k4 * 4) * H;
            float wa0 = wr[c0],         wa1 = wr[H + c0],
                  wa2 = wr[2 * H + c0], wa3 = wr[3 * H + c0];
            float wb0 = wr[c0 + 64],         wb1 = wr[H + c0 + 64],
                  wb2 = wr[2 * H + c0 + 64], wb3 = wr[3 * H + c0 + 64];
#pragma unroll
            for (int e = 0; e < 16; e++) {
                float4 x = h14[eh * 16 + e][k4];
                acc0[e] = fmaf(x.x, wa0, acc0[e]); acc0[e] = fmaf(x.y, wa1, acc0[e]);
                acc0[e] = fmaf(x.z, wa2, acc0[e]); acc0[e] = fmaf(x.w, wa3, acc0[e]);
                acc1[e] = fmaf(x.x, wb0, acc1[e]); acc1[e] = fmaf(x.y, wb1, acc1[e]);
                acc1[e] = fmaf(x.z, wb2, acc1[e]); acc1[e] = fmaf(x.w, wb3, acc1[e]);
            }
        }
        {
            float bb0 = b2a[gi * H + c0], bb1 = b2a[gi * H + c0 + 64];
            float* h2f = (float*)h24;
#pragma unroll
            for (int e = 0; e < 16; e++) {
                int ge = eh * 16 + e;
                h2f[ge * H + c0]      = fmaxf(acc0[e] + bb0, 0.f);
                h2f[ge * H + c0 + 64] = fmaxf(acc1[e] + bb1, 0.f);
            }
        }
        __syncthreads();

        // ---- layer 3 -> scatter-add ----
#pragma unroll
        for (int e = 0; e < 16; e++) { acc0[e] = 0.f; acc1[e] = 0.f; }
        for (int k4 = 0; k4 < H / 4; k4++) {
            const float* wr = w3 + (k4 * 4) * H;
            float wa0 = wr[c0],         wa1 = wr[H + c0],
                  wa2 = wr[2 * H + c0], wa3 = wr[3 * H + c0];
            float wb0 = wr[c0 + 64],         wb1 = wr[H + c0 + 64],
                  wb2 = wr[2 * H + c0 + 64], wb3 = wr[3 * H + c0 + 64];
#pragma unroll
            for (int e = 0; e < 16; e++) {
                float4 x = h24[eh * 16 + e][k4];
                acc0[e] = fmaf(x.x, wa0, acc0[e]); acc0[e] = fmaf(x.y, wa1, acc0[e]);
                acc0[e] = fmaf(x.z, wa2, acc0[e]); acc0[e] = fmaf(x.w, wa3, acc0[e]);
                acc1[e] = fmaf(x.x, wb0, acc1[e]); acc1[e] = fmaf(x.y, wb1, acc1[e]);
                acc1[e] = fmaf(x.z, wb2, acc1[e]); acc1[e] = fmaf(x.w, wb3, acc1[e]);
            }
        }
        {
            float bb0 = b3a[gi * H + c0], bb1 = b3a[gi * H + c0 + 64];
            for (int e = 0; e < 16; e++) {
                int ge = eh * 16 + e;
                if (ge < ne) {
                    int d = sdst[ge];
                    atomicAdd(&g_msg[(size_t)d * H + c0],      acc0[e] + bb0);
                    atomicAdd(&g_msg[(size_t)d * H + c0 + 64], acc1[e] + bb1);
                }
            }
        }
        __syncthreads();
    }
}

// ---------------- fused per-level GRU kernel (R8-proven) -------------------
// h_old is provably zero (each node updated exactly once): whh GEMM -> bhh bias.
__global__ void __launch_bounds__(128) k_gru_lvl(
        const float* __restrict__ bih_a, const float* __restrict__ bhh_a,
        float* __restrict__ outbuf, int lvl) {
    __shared__ float4 ms4[GRU_TN][H / 4];    // 8 KB
    __shared__ int snode[GRU_TN];

    const int b0 = (lvl - 1) * 3;
    const int t0 = g_ntile[b0];
    const int t3 = g_ntile[b0 + 3];
    const int tid = threadIdx.x;
    const int lane = tid & 31, wrp = tid >> 5;
    const int j = tid;
    float* hf = outbuf + (size_t)N_NODES * H;

    for (int g = t0 + blockIdx.x; g < t3; g += gridDim.x) {
        int b = b0;
        while (b < b0 + 2 && g >= g_ntile[b + 1]) b++;
        const int gi = b - b0;
        const int nstart = g_noff[b] + (g - g_ntile[b]) * GRU_TN;
        const int nn = min(GRU_TN, g_noff[b + 1] - nstart);
        const float* __restrict__ wihT = g_wihT + (size_t)gi * H * H3;

        if (tid < GRU_TN)
            snode[tid] = (tid < nn) ? g_nlist[nstart + tid] : -1;
        __syncthreads();

        for (int p = wrp; p < GRU_TN; p += 4) {
            int node = snode[p];
            float4 v = make_float4(0.f, 0.f, 0.f, 0.f);
            if (node >= 0) v = ((const float4*)(g_msg + (size_t)node * H))[lane];
            ms4[p][lane] = v;
        }
        __syncthreads();

        float ar[GRU_TN], az[GRU_TN], an[GRU_TN];
#pragma unroll
        for (int e = 0; e < GRU_TN; e++) { ar[e] = 0.f; az[e] = 0.f; an[e] = 0.f; }

        for (int k4 = 0; k4 < H / 4; k4++) {
            const float* wr = wihT + (size_t)(k4 * 4) * H3;
            float r0 = wr[j],            r1 = wr[H3 + j],
                  r2 = wr[2 * H3 + j],   r3 = wr[3 * H3 + j];
            float z0 = wr[H + j],           z1 = wr[H3 + H + j],
                  z2 = wr[2 * H3 + H + j],  z3 = wr[3 * H3 + H + j];
            float n0 = wr[2 * H + j],          n1 = wr[H3 + 2 * H + j],
                  n2 = wr[2 * H3 + 2 * H + j], n3 = wr[3 * H3 + 2 * H + j];
#pragma unroll
            for (int e = 0; e < GRU_TN; e++) {
                float4 m = ms4[e][k4];
                ar[e] = fmaf(m.x, r0, ar[e]); ar[e] = fmaf(m.y, r1, ar[e]);
                ar[e] = fmaf(m.z, r2, ar[e]); ar[e] = fmaf(m.w, r3, ar[e]);
                az[e] = fmaf(m.x, z0, az[e]); az[e] = fmaf(m.y, z1, az[e]);
                az[e] = fmaf(m.z, z2, az[e]); az[e] = fmaf(m.w, z3, az[e]);
                an[e] = fmaf(m.x, n0, an[e]); an[e] = fmaf(m.y, n1, an[e]);
                an[e] = fmaf(m.z, n2, an[e]); an[e] = fmaf(m.w, n3, an[e]);
            }
        }

        const float bir = bih_a[gi * H3 + j]     + bhh_a[gi * H3 + j];
        const float biz = bih_a[gi * H3 + H + j] + bhh_a[gi * H3 + H + j];
        const float bin_ = bih_a[gi * H3 + 2 * H + j];
        const float bhn  = bhh_a[gi * H3 + 2 * H + j];
        for (int e = 0; e < GRU_TN; e++) {
            int node = snode[e];
            if (node >= 0) {
                float r = 1.0f / (1.0f + expf(-(ar[e] + bir)));
                float z = 1.0f / (1.0f + expf(-(az[e] + biz)));
                float nst = tanhf(an[e] + bin_ + r * bhn);
                hf[(size_t)node * H + j] = (1.0f - z) * nst;
            }
        }
        __syncthreads();
    }
}

// ---------------- launch ---------------------------------------------------

extern "C" void kernel_launch(void* const* d_in, const int* in_sizes, int n_in,
                              void* d_out, int out_size) {
    const int* gate    = (const int*)d_in[0];
    const int* flevel  = (const int*)d_in[1];
    const int* ei      = (const int*)d_in[2];
    const float* Ws    = (const float*)d_in[3];
    const float* Wt    = (const float*)d_in[4];
    const float* hs_W  = (const float*)d_in[5];
    const float* hs_b  = (const float*)d_in[6];
    const float* w1    = (const float*)d_in[7];
    const float* b1    = (const float*)d_in[8];
    const float* w2    = (const float*)d_in[9];
    const float* b2    = (const float*)d_in[10];
    const float* w3    = (const float*)d_in[11];
    const float* b3    = (const float*)d_in[12];
    const float* wih   = (const float*)d_in[13];
    const float* bih   = (const float*)d_in[15];
    const float* bhh   = (const float*)d_in[16];
    float* out = (float*)d_out;

    // 3 fused setup launches (counters re-zeroed by k_setup2 for next replay)
    k_setup0<<<1030, 256>>>(Ws, Wt, hs_W, hs_b, wih, ei, gate, flevel);
    k_setup1<<<18, 128>>>(w1);
    k_setup2<<<2080, 256>>>((float4*)out, gate, ei, flevel);

    // R8-proven schedule: per level, msg over the 6 (gi x z) sub-buckets,
    // then GRU over the level's nodes.
    for (int lvl = 1; lvl <= NLVL; lvl++) {
        k_msg_range<<<1184, 128>>>(ei, gate, out, w1, b1, w2, b2, w3, b3,
                                   (lvl - 1) * 6, 6);
        k_gru_lvl<<<1184, 128>>>(bih, bhh, out, lvl);
    }
}

// round 16
// speedup vs baseline: 1.1329x; 1.0148x over previous
#include <cuda_runtime.h>
#include <math.h>

#define N_NODES 100000
#define N_EDGES 200000
#define H 128
#define H2 256
#define H3 384
#define NLVL 7
#define NBUCK_E 42        // (l-1)*6 + gi*2 + z ; z=1 -> hf[src] statically zero
#define NBUCK_N 21        // (l-1)*3 + gi
#define NCNT (NBUCK_E + NBUCK_N)
#define MSG_TE 32         // edges per msg tile
#define GRU_TN 16         // nodes per gru tile

// ---------------- device scratch (static: no allocations allowed) ----------
__device__ float g_msg[(size_t)N_NODES * H];   // scatter-add target
__device__ float g_hs_type[6 * H];             // per-gate-type hs row
__device__ float g_hsl1[3 * 6 * H];            // layer1 hs-half table [gi][gtype][j]
__device__ float g_wihT[3 * H * H3];           // transposed GRU input weights [gi][k][row]
__device__ int g_cnt[NCNT];                    // bucket counts; re-zeroed by k_setup2
__device__ int g_eoff[NBUCK_E + 1];
__device__ int g_ecur[NBUCK_E];
__device__ int g_etile[NBUCK_E + 1];
__device__ int g_noff[NBUCK_N + 1];
__device__ int g_ncur[NBUCK_N];
__device__ int g_ntile[NBUCK_N + 1];
__device__ int g_elist[N_EDGES];
__device__ int g_nlist[N_NODES];

__device__ __forceinline__ int gate_gi(int g) {
    // GATE_CODES = (3, 2, 5) -> gi 0, 1, 2
    return (g == 3) ? 0 : (g == 2) ? 1 : (g == 5) ? 2 : -1;
}

// edge bucket: (l-1)*6 + gi*2 + z   (z=1: hf[src] statically zero)
__device__ __forceinline__ int edge_bucket(int src, int dst,
                                           const int* gate, const int* lvl) {
    int gi = gate_gi(gate[dst]);
    int l = lvl[dst];
    if (gi < 0 || l < 1 || l > NLVL) return -1;
    int gs = gate_gi(gate[src]);
    int ls = lvl[src];
    int z = !(gs >= 0 && ls >= 1 && ls < l);
    return (l - 1) * 6 + gi * 2 + z;
}

// ---------------- K0: hs_type + wih transpose + bucket count --------------
__global__ void k_setup0(const float* __restrict__ Ws, const float* __restrict__ Wt,
                         const float* __restrict__ hsW, const float* __restrict__ hsb,
                         const float* __restrict__ wih,
                         const int* __restrict__ ei, const int* __restrict__ gate,
                         const int* __restrict__ lvl) {
    if (blockIdx.x < 6) {
        int g = blockIdx.x;
        int j = threadIdx.x;
        if (j < H) {
            float acc = hsb[j];
#pragma unroll 4
            for (int k = 0; k < H; k++)
                acc = fmaf(Ws[g * H + k], hsW[k * H + j], acc);
#pragma unroll 4
            for (int k = 0; k < H; k++)
                acc = fmaf(Wt[g * H + k], hsW[(H + k) * H + j], acc);
            g_hs_type[g * H + j] = acc;
        }
        return;
    }
    const int TT = 3 * H3 * H;                 // transpose items
    const int total = TT + N_EDGES + N_NODES;  // + count items
    const int stride = (gridDim.x - 6) * blockDim.x;
    for (int i = (blockIdx.x - 6) * blockDim.x + threadIdx.x; i < total; i += stride) {
        if (i < TT) {
            int gi = i / (H3 * H);
            int rem = i - gi * (H3 * H);
            int r = rem / H;
            int k = rem - r * H;
            g_wihT[gi * H * H3 + k * H3 + r] = wih[i];
        } else {
            int w = i - TT;
            if (w < N_EDGES) {
                int b = edge_bucket(ei[w], ei[N_EDGES + w], gate, lvl);
                if (b >= 0) atomicAdd(&g_cnt[b], 1);
            } else {
                int n = w - N_EDGES;
                int gi = gate_gi(gate[n]);
                int l = lvl[n];
                if (gi >= 0 && l >= 1 && l <= NLVL)
                    atomicAdd(&g_cnt[NBUCK_E + (l - 1) * 3 + gi], 1);
            }
        }
    }
}

// ---------------- K1: hsl1 table + scan ------------------------------------
__global__ void k_setup1(const float* __restrict__ w1) {
    int gi = blockIdx.x / 6;
    int g = blockIdx.x % 6;
    int j = threadIdx.x;
    const float* w = w1 + (size_t)gi * H2 * H;
    float acc = 0.f;
#pragma unroll 4
    for (int k = 0; k < H; k++)
        acc = fmaf(g_hs_type[g * H + k], w[k * H + j], acc);
    g_hsl1[(gi * 6 + g) * H + j] = acc;

    if (blockIdx.x == 0 && j == 0) {
        int s = 0, st = 0;
        for (int b = 0; b < NBUCK_E; b++) {
            g_eoff[b] = s; g_ecur[b] = s; g_etile[b] = st;
            st += (g_cnt[b] + MSG_TE - 1) / MSG_TE;
            s += g_cnt[b];
        }
        g_eoff[NBUCK_E] = s; g_etile[NBUCK_E] = st;
        s = 0; st = 0;
        for (int b = 0; b < NBUCK_N; b++) {
            g_noff[b] = s; g_ncur[b] = s; g_ntile[b] = st;
            st += (g_cnt[NBUCK_E + b] + GRU_TN - 1) / GRU_TN;
            s += g_cnt[NBUCK_E + b];
        }
        g_noff[NBUCK_N] = s; g_ntile[NBUCK_N] = st;
    }
}

// ---------------- K2: hs_fill + fill_lists + counter re-zero ---------------
__global__ void k_setup2(float4* __restrict__ out4, const int* __restrict__ gate,
                         const int* __restrict__ ei, const int* __restrict__ lvl) {
    if (blockIdx.x == 0 && threadIdx.x < NCNT) g_cnt[threadIdx.x] = 0;

    const int F4 = N_NODES * (H / 4);
    const int total = F4 + N_EDGES + N_NODES;
    const float4* hs4 = (const float4*)g_hs_type;
    float4* msg4 = (float4*)g_msg;
    const float4 z4 = make_float4(0.f, 0.f, 0.f, 0.f);
    for (int i = blockIdx.x * blockDim.x + threadIdx.x; i < total; i += gridDim.x * blockDim.x) {
        if (i < F4) {
            int node = i >> 5;
            int c = i & 31;
            out4[i] = hs4[gate[node] * 32 + c];
            out4[F4 + i] = z4;
            msg4[i] = z4;
        } else {
            int w = i - F4;
            if (w < N_EDGES) {
                int b = edge_bucket(ei[w], ei[N_EDGES + w], gate, lvl);
                if (b >= 0) {
                    int pos = atomicAdd(&g_ecur[b], 1);
                    g_elist[pos] = w;
                }
            } else {
                int n = w - N_EDGES;
                int gi = gate_gi(gate[n]);
                int l = lvl[n];
                if (gi >= 0 && l >= 1 && l <= NLVL) {
                    int pos = atomicAdd(&g_ncur[(l - 1) * 3 + gi], 1);
                    g_nlist[pos] = n;
                }
            }
        }
    }
}

// ---------------- per-level message kernel (256 thr, high occupancy) -------
// Processes edge buckets [bBase, bBase+bCnt). Block = 256 threads, tile = 32
// edges; thread owns ONE column (c0 = tid & 127) x 16 edges (eh = tid >> 7).
// Smem: xbuf (hf stage, reused for h2) + h1buf = 32KB -> 3 blocks/SM
// (with __launch_bounds__(256,3) reg cap 85) = 24 warps/SM.
__global__ void __launch_bounds__(256, 3) k_msg_range(
        const int* __restrict__ ei, const int* __restrict__ gate,
        const float* __restrict__ outbuf,
        const float* __restrict__ w1a, const float* __restrict__ b1a,
        const float* __restrict__ w2a, const float* __restrict__ b2a,
        const float* __restrict__ w3a, const float* __restrict__ b3a,
        int bBase, int bCnt) {
    __shared__ float4 xbuf[MSG_TE][H / 4];   // 16 KB: hf stage; reused for h2
    __shared__ float4 h1buf[MSG_TE][H / 4];  // 16 KB
    __shared__ int ssrc[MSG_TE];
    __shared__ int sdst[MSG_TE];
    __shared__ int sgt[MSG_TE];

    const int t0 = g_etile[bBase];
    const int tN = g_etile[bBase + bCnt];
    const int tid = threadIdx.x;
    const int lane = tid & 31, wrp = tid >> 5;   // 8 warps
    const int c0 = tid & 127;                    // owned column
    const int eh = tid >> 7;                     // edge half: 0 or 1
    const float* hf = outbuf + (size_t)N_NODES * H;

    for (int g = t0 + blockIdx.x; g < tN; g += gridDim.x) {
        int b = bBase;
        while (b < bBase + bCnt - 1 && g >= g_etile[b + 1]) b++;
        const int sub = b - bBase;
        const int gi = sub >> 1;
        const int hfz = sub & 1;             // 1 -> hf[src] statically zero
        const int estart = g_eoff[b] + (g - g_etile[b]) * MSG_TE;
        const int ne = min(MSG_TE, g_eoff[b + 1] - estart);
        const float* __restrict__ w1 = w1a + (size_t)gi * H2 * H;
        const float* __restrict__ w2 = w2a + (size_t)gi * H * H;
        const float* __restrict__ w3 = w3a + (size_t)gi * H * H;
        const float* __restrict__ tbl = g_hsl1 + (size_t)gi * 6 * H;

        // ---- stage edge endpoints + src gate type ----
        if (tid < MSG_TE) {
            if (tid < ne) {
                int eid = g_elist[estart + tid];
                int src = ei[eid];
                ssrc[tid] = src;
                sdst[tid] = ei[N_EDGES + eid];
                sgt[tid] = gate[src];
            } else {
                ssrc[tid] = -1;
                sgt[tid] = 0;
            }
        }
        __syncthreads();

        float acc[16];
        // ---- layer 1 -> h1buf ----
        if (hfz) {
            float bb = b1a[gi * H + c0];
            float* h1f = (float*)h1buf;
#pragma unroll
            for (int e = 0; e < 16; e++) {
                int gt = sgt[eh * 16 + e];
                h1f[(eh * 16 + e) * H + c0] =
                    fmaxf(__ldg(&tbl[gt * H + c0]) + bb, 0.f);
            }
        } else {
            // gather hf[src] (float4, coalesced per warp; 8 warps x 4 rows)
            for (int p = wrp; p < MSG_TE; p += 8) {
                int src = ssrc[p];
                float4 v = make_float4(0.f, 0.f, 0.f, 0.f);
                if (src >= 0) v = ((const float4*)(hf + (size_t)src * H))[lane];
                xbuf[p][lane] = v;
            }
#pragma unroll
            for (int e = 0; e < 16; e++) {
                int gt = sgt[eh * 16 + e];
                acc[e] = __ldg(&tbl[gt * H + c0]);
            }
            __syncthreads();
            const float* w1b = w1 + (size_t)H * H;   // hf half: rows 128..255
            for (int k4 = 0; k4 < H / 4; k4++) {
                const float* wr = w1b + (k4 * 4) * H;
                float wa0 = wr[c0],         wa1 = wr[H + c0],
                      wa2 = wr[2 * H + c0], wa3 = wr[3 * H + c0];
#pragma unroll
                for (int e = 0; e < 16; e++) {
                    float4 x = xbuf[eh * 16 + e][k4];
                    acc[e] = fmaf(x.x, wa0, acc[e]); acc[e] = fmaf(x.y, wa1, acc[e]);
                    acc[e] = fmaf(x.z, wa2, acc[e]); acc[e] = fmaf(x.w, wa3, acc[e]);
                }
            }
            float bb = b1a[gi * H + c0];
            float* h1f = (float*)h1buf;
#pragma unroll
            for (int e = 0; e < 16; e++)
                h1f[(eh * 16 + e) * H + c0] = fmaxf(acc[e] + bb, 0.f);
        }
        __syncthreads();

        // ---- layer 2: h1buf -> h2 (stored in xbuf) ----
#pragma unroll
        for (int e = 0; e < 16; e++) acc[e] = 0.f;
        for (int k4 = 0; k4 < H / 4; k4++) {
            const float* wr = w2 + (k4 * 4) * H;
            float wa0 = wr[c0],         wa1 = wr[H + c0],
                  wa2 = wr[2 * H + c0], wa3 = wr[3 * H + c0];
#pragma unroll
            for (int e = 0; e < 16; e++) {
                float4 x = h1buf[eh * 16 + e][k4];
                acc[e] = fmaf(x.x, wa0, acc[e]); acc[e] = fmaf(x.y, wa1, acc[e]);
                acc[e] = fmaf(x.z, wa2, acc[e]); acc[e] = fmaf(x.w, wa3, acc[e]);
            }
        }
        __syncthreads();   // layer-1 reads of xbuf are done; safe to overwrite
        {
            float bb = b2a[gi * H + c0];
            float* h2f = (float*)xbuf;
#pragma unroll
            for (int e = 0; e < 16; e++)
                h2f[(eh * 16 + e) * H + c0] = fmaxf(acc[e] + bb, 0.f);
        }
        __syncthreads();

        // ---- layer 3: xbuf(h2) -> scatter-add ----
#pragma unroll
        for (int e = 0; e < 16; e++) acc[e] = 0.f;
        for (int k4 = 0; k4 < H / 4; k4++) {
            const float* wr = w3 + (k4 * 4) * H;
            float wa0 = wr[c0],         wa1 = wr[H + c0],
                  wa2 = wr[2 * H + c0], wa3 = wr[3 * H + c0];
#pragma unroll
            for (int e = 0; e < 16; e++) {
                float4 x = xbuf[eh * 16 + e][k4];
                acc[e] = fmaf(x.x, wa0, acc[e]); acc[e] = fmaf(x.y, wa1, acc[e]);
                acc[e] = fmaf(x.z, wa2, acc[e]); acc[e] = fmaf(x.w, wa3, acc[e]);
            }
        }
        {
            float bb = b3a[gi * H + c0];
            for (int e = 0; e < 16; e++) {
                int ge = eh * 16 + e;
                if (ge < ne)
                    atomicAdd(&g_msg[(size_t)sdst[ge] * H + c0], acc[e] + bb);
            }
        }
        __syncthreads();
    }
}

// ---------------- fused per-level GRU kernel (R8-proven) -------------------
__global__ void __launch_bounds__(128) k_gru_lvl(
        const float* __restrict__ bih_a, const float* __restrict__ bhh_a,
        float* __restrict__ outbuf, int lvl) {
    __shared__ float4 ms4[GRU_TN][H / 4];    // 8 KB
    __shared__ int snode[GRU_TN];

    const int b0 = (lvl - 1) * 3;
    const int t0 = g_ntile[b0];
    const int t3 = g_ntile[b0 + 3];
    const int tid = threadIdx.x;
    const int lane = tid & 31, wrp = tid >> 5;
    const int j = tid;
    float* hf = outbuf + (size_t)N_NODES * H;

    for (int g = t0 + blockIdx.x; g < t3; g += gridDim.x) {
        int b = b0;
        while (b < b0 + 2 && g >= g_ntile[b + 1]) b++;
        const int gi = b - b0;
        const int nstart = g_noff[b] + (g - g_ntile[b]) * GRU_TN;
        const int nn = min(GRU_TN, g_noff[b + 1] - nstart);
        const float* __restrict__ wihT = g_wihT + (size_t)gi * H * H3;

        if (tid < GRU_TN)
            snode[tid] = (tid < nn) ? g_nlist[nstart + tid] : -1;
        __syncthreads();

        for (int p = wrp; p < GRU_TN; p += 4) {
            int node = snode[p];
            float4 v = make_float4(0.f, 0.f, 0.f, 0.f);
            if (node >= 0) v = ((const float4*)(g_msg + (size_t)node * H))[lane];
            ms4[p][lane] = v;
        }
        __syncthreads();

        float ar[GRU_TN], az[GRU_TN], an[GRU_TN];
#pragma unroll
        for (int e = 0; e < GRU_TN; e++) { ar[e] = 0.f; az[e] = 0.f; an[e] = 0.f; }

        for (int k4 = 0; k4 < H / 4; k4++) {
            const float* wr = wihT + (size_t)(k4 * 4) * H3;
            float r0 = wr[j],            r1 = wr[H3 + j],
                  r2 = wr[2 * H3 + j],   r3 = wr[3 * H3 + j];
            float z0 = wr[H + j],           z1 = wr[H3 + H + j],
                  z2 = wr[2 * H3 + H + j],  z3 = wr[3 * H3 + H + j];
            float n0 = wr[2 * H + j],          n1 = wr[H3 + 2 * H + j],
                  n2 = wr[2 * H3 + 2 * H + j], n3 = wr[3 * H3 + 2 * H + j];
#pragma unroll
            for (int e = 0; e < GRU_TN; e++) {
                float4 m = ms4[e][k4];
                ar[e] = fmaf(m.x, r0, ar[e]); ar[e] = fmaf(m.y, r1, ar[e]);
                ar[e] = fmaf(m.z, r2, ar[e]); ar[e] = fmaf(m.w, r3, ar[e]);
                az[e] = fmaf(m.x, z0, az[e]); az[e] = fmaf(m.y, z1, az[e]);
                az[e] = fmaf(m.z, z2, az[e]); az[e] = fmaf(m.w, z3, az[e]);
                an[e] = fmaf(m.x, n0, an[e]); an[e] = fmaf(m.y, n1, an[e]);
                an[e] = fmaf(m.z, n2, an[e]); an[e] = fmaf(m.w, n3, an[e]);
            }
        }

        const float bir = bih_a[gi * H3 + j]     + bhh_a[gi * H3 + j];
        const float biz = bih_a[gi * H3 + H + j] + bhh_a[gi * H3 + H + j];
        const float bin_ = bih_a[gi * H3 + 2 * H + j];
        const float bhn  = bhh_a[gi * H3 + 2 * H + j];
        for (int e = 0; e < GRU_TN; e++) {
            int node = snode[e];
            if (node >= 0) {
                float r = 1.0f / (1.0f + expf(-(ar[e] + bir)));
                float z = 1.0f / (1.0f + expf(-(az[e] + biz)));
                float nst = tanhf(an[e] + bin_ + r * bhn);
                hf[(size_t)node * H + j] = (1.0f - z) * nst;
            }
        }
        __syncthreads();
    }
}

// ---------------- launch ---------------------------------------------------

extern "C" void kernel_launch(void* const* d_in, const int* in_sizes, int n_in,
                              void* d_out, int out_size) {
    const int* gate    = (const int*)d_in[0];
    const int* flevel  = (const int*)d_in[1];
    const int* ei      = (const int*)d_in[2];
    const float* Ws    = (const float*)d_in[3];
    const float* Wt    = (const float*)d_in[4];
    const float* hs_W  = (const float*)d_in[5];
    const float* hs_b  = (const float*)d_in[6];
    const float* w1    = (const float*)d_in[7];
    const float* b1    = (const float*)d_in[8];
    const float* w2    = (const float*)d_in[9];
    const float* b2    = (const float*)d_in[10];
    const float* w3    = (const float*)d_in[11];
    const float* b3    = (const float*)d_in[12];
    const float* wih   = (const float*)d_in[13];
    const float* bih   = (const float*)d_in[15];
    const float* bhh   = (const float*)d_in[16];
    float* out = (float*)d_out;

    k_setup0<<<1030, 256>>>(Ws, Wt, hs_W, hs_b, wih, ei, gate, flevel);
    k_setup1<<<18, 128>>>(w1);
    k_setup2<<<2080, 256>>>((float4*)out, gate, ei, flevel);

    for (int lvl = 1; lvl <= NLVL; lvl++) {
        k_msg_range<<<888, 256>>>(ei, gate, out, w1, b1, w2, b2, w3, b3,
                                  (lvl - 1) * 6, 6);
        k_gru_lvl<<<1184, 128>>>(bih, bhh, out, lvl);
    }
}

// round 17
// speedup vs baseline: 1.2647x; 1.1163x over previous
#include <cuda_runtime.h>
#include <math.h>

#define N_NODES 100000
#define N_EDGES 200000
#define H 128
#define H2 256
#define H3 384
#define NLVL 7
#define NBUCK_E 21        // z0 edges only: (l-1)*3 + gi
#define NBUCK_N 21        // (l-1)*3 + gi
#define NCNT (NBUCK_E + NBUCK_N)
#define MSG_TE 32         // edges per msg tile
#define GRU_TN 16         // nodes per gru tile

// ---------------- device scratch (static: no allocations allowed) ----------
__device__ float g_msg[(size_t)N_NODES * H];   // z0 scatter-add target
__device__ float g_hs_type[6 * H];             // per-gate-type hs row
__device__ float g_hsl1[3 * 6 * H];            // layer1 hs-half table [gi][gtype][j]
__device__ float g_mout[3 * 6 * H];            // FULL MLP output table [gi][gtype][j]
__device__ float g_wihT[3 * H * H3];           // transposed GRU input weights [gi][k][row]
__device__ int g_z1cnt[(size_t)N_NODES * 6];   // z1 in-edge counts per (node, src gate);
                                               // zero at load, self-reset by k_gru_lvl
__device__ int g_cnt[NCNT];                    // bucket counts; re-zeroed by k_setup2
__device__ int g_eoff[NBUCK_E + 1];
__device__ int g_ecur[NBUCK_E];
__device__ int g_etile[NBUCK_E + 1];
__device__ int g_noff[NBUCK_N + 1];
__device__ int g_ncur[NBUCK_N];
__device__ int g_ntile[NBUCK_N + 1];
__device__ int g_elist[N_EDGES];
__device__ int g_nlist[N_NODES];

__device__ __forceinline__ int gate_gi(int g) {
    // GATE_CODES = (3, 2, 5) -> gi 0, 1, 2
    return (g == 3) ? 0 : (g == 2) ? 1 : (g == 5) ? 2 : -1;
}

// ---------------- K0: hs_type + wih transpose + edge/node classification ---
__global__ void k_setup0(const float* __restrict__ Ws, const float* __restrict__ Wt,
                         const float* __restrict__ hsW, const float* __restrict__ hsb,
                         const float* __restrict__ wih,
                         const int* __restrict__ ei, const int* __restrict__ gate,
                         const int* __restrict__ lvl) {
    if (blockIdx.x < 6) {
        int g = blockIdx.x;
        int j = threadIdx.x;
        if (j < H) {
            float acc = hsb[j];
#pragma unroll 4
            for (int k = 0; k < H; k++)
                acc = fmaf(Ws[g * H + k], hsW[k * H + j], acc);
#pragma unroll 4
            for (int k = 0; k < H; k++)
                acc = fmaf(Wt[g * H + k], hsW[(H + k) * H + j], acc);
            g_hs_type[g * H + j] = acc;
        }
        return;
    }
    const int TT = 3 * H3 * H;                 // transpose items
    const int total = TT + N_EDGES + N_NODES;  // + classify items
    const int stride = (gridDim.x - 6) * blockDim.x;
    for (int i = (blockIdx.x - 6) * blockDim.x + threadIdx.x; i < total; i += stride) {
        if (i < TT) {
            int gi = i / (H3 * H);
            int rem = i - gi * (H3 * H);
            int r = rem / H;
            int k = rem - r * H;
            g_wihT[gi * H * H3 + k * H3 + r] = wih[i];
        } else {
            int w = i - TT;
            if (w < N_EDGES) {
                int src = ei[w];
                int dst = ei[N_EDGES + w];
                int gi = gate_gi(gate[dst]);
                int l = lvl[dst];
                if (gi >= 0 && l >= 1 && l <= NLVL) {
                    int gs = gate_gi(gate[src]);
                    int ls = lvl[src];
                    if (gs >= 0 && ls >= 1 && ls < l) {
                        // z0 edge: needs per-level MLP on hf[src]
                        atomicAdd(&g_cnt[(l - 1) * 3 + gi], 1);
                    } else {
                        // z1 edge: message is a pure function of gate[src]
                        atomicAdd(&g_z1cnt[(size_t)dst * 6 + gate[src]], 1);
                    }
                }
            } else {
                int n = w - N_EDGES;
                int gi = gate_gi(gate[n]);
                int l = lvl[n];
                if (gi >= 0 && l >= 1 && l <= NLVL)
                    atomicAdd(&g_cnt[NBUCK_E + (l - 1) * 3 + gi], 1);
            }
        }
    }
}

// ---------------- K1: hsl1 table + scan ------------------------------------
__global__ void k_setup1(const float* __restrict__ w1) {
    int gi = blockIdx.x / 6;
    int g = blockIdx.x % 6;
    int j = threadIdx.x;
    const float* w = w1 + (size_t)gi * H2 * H;
    float acc = 0.f;
#pragma unroll 4
    for (int k = 0; k < H; k++)
        acc = fmaf(g_hs_type[g * H + k], w[k * H + j], acc);
    g_hsl1[(gi * 6 + g) * H + j] = acc;

    if (blockIdx.x == 0 && j == 0) {
        int s = 0, st = 0;
        for (int b = 0; b < NBUCK_E; b++) {
            g_eoff[b] = s; g_ecur[b] = s; g_etile[b] = st;
            st += (g_cnt[b] + MSG_TE - 1) / MSG_TE;
            s += g_cnt[b];
        }
        g_eoff[NBUCK_E] = s; g_etile[NBUCK_E] = st;
        s = 0; st = 0;
        for (int b = 0; b < NBUCK_N; b++) {
            g_noff[b] = s; g_ncur[b] = s; g_ntile[b] = st;
            st += (g_cnt[NBUCK_E + b] + GRU_TN - 1) / GRU_TN;
            s += g_cnt[NBUCK_E + b];
        }
        g_noff[NBUCK_N] = s; g_ntile[NBUCK_N] = st;
    }
}

// ---------------- K2: mout table + hs_fill + z0 list fill + cnt re-zero ----
__global__ void k_setup2(float4* __restrict__ out4, const int* __restrict__ gate,
                         const int* __restrict__ ei, const int* __restrict__ lvl,
                         const float* __restrict__ b1a,
                         const float* __restrict__ w2a, const float* __restrict__ b2a,
                         const float* __restrict__ w3a, const float* __restrict__ b3a) {
    // Blocks 0..17: compute the full-MLP table mout[gi][gt][:] (z1 messages)
    if (blockIdx.x < 18) {
        __shared__ float ha[H], hb[H];
        int gi = blockIdx.x / 6;
        int gt = blockIdx.x % 6;
        int j = threadIdx.x;
        if (j < H)
            ha[j] = fmaxf(g_hsl1[(gi * 6 + gt) * H + j] + b1a[gi * H + j], 0.f);
        __syncthreads();
        if (j < H) {
            const float* w2 = w2a + (size_t)gi * H * H;
            float acc = b2a[gi * H + j];
#pragma unroll 4
            for (int k = 0; k < H; k++)
                acc = fmaf(ha[k], w2[k * H + j], acc);
            hb[j] = fmaxf(acc, 0.f);
        }
        __syncthreads();
        if (j < H) {
            const float* w3 = w3a + (size_t)gi * H * H;
            float acc = b3a[gi * H + j];
#pragma unroll 4
            for (int k = 0; k < H; k++)
                acc = fmaf(hb[k], w3[k * H + j], acc);
            g_mout[(gi * 6 + gt) * H + j] = acc;
        }
        __syncthreads();
    }

    if (blockIdx.x == 0 && threadIdx.x < NCNT) g_cnt[threadIdx.x] = 0;

    const int F4 = N_NODES * (H / 4);
    const int total = F4 + N_EDGES + N_NODES;
    const float4* hs4 = (const float4*)g_hs_type;
    float4* msg4 = (float4*)g_msg;
    const float4 z4 = make_float4(0.f, 0.f, 0.f, 0.f);
    for (int i = blockIdx.x * blockDim.x + threadIdx.x; i < total; i += gridDim.x * blockDim.x) {
        if (i < F4) {
            int node = i >> 5;
            int c = i & 31;
            out4[i] = hs4[gate[node] * 32 + c];
            out4[F4 + i] = z4;
            msg4[i] = z4;
        } else {
            int w = i - F4;
            if (w < N_EDGES) {
                int src = ei[w];
                int dst = ei[N_EDGES + w];
                int gi = gate_gi(gate[dst]);
                int l = lvl[dst];
                if (gi >= 0 && l >= 1 && l <= NLVL) {
                    int gs = gate_gi(gate[src]);
                    int ls = lvl[src];
                    if (gs >= 0 && ls >= 1 && ls < l) {
                        int pos = atomicAdd(&g_ecur[(l - 1) * 3 + gi], 1);
                        g_elist[pos] = w;
                    }
                }
            } else {
                int n = w - N_EDGES;
                int gi = gate_gi(gate[n]);
                int l = lvl[n];
                if (gi >= 0 && l >= 1 && l <= NLVL) {
                    int pos = atomicAdd(&g_ncur[(l - 1) * 3 + gi], 1);
                    g_nlist[pos] = n;
                }
            }
        }
    }
}

// ---------------- z0 message kernel (levels 2..7) --------------------------
// Block = 256 threads, tile = 32 edges; thread owns ONE column x 16 edges.
// layer1 = hsl1[gate[src]] + hf[src] @ w1[128:256] + b1 (all tiles read hf).
__global__ void __launch_bounds__(256, 3) k_msg_range(
        const int* __restrict__ ei, const int* __restrict__ gate,
        const float* __restrict__ outbuf,
        const float* __restrict__ w1a, const float* __restrict__ b1a,
        const float* __restrict__ w2a, const float* __restrict__ b2a,
        const float* __restrict__ w3a, const float* __restrict__ b3a,
        int bBase, int bCnt) {
    __shared__ float4 xbuf[MSG_TE][H / 4];   // 16 KB: hf stage; reused for h2
    __shared__ float4 h1buf[MSG_TE][H / 4];  // 16 KB
    __shared__ int ssrc[MSG_TE];
    __shared__ int sdst[MSG_TE];
    __shared__ int sgt[MSG_TE];

    const int t0 = g_etile[bBase];
    const int tN = g_etile[bBase + bCnt];
    const int tid = threadIdx.x;
    const int lane = tid & 31, wrp = tid >> 5;   // 8 warps
    const int c0 = tid & 127;                    // owned column
    const int eh = tid >> 7;                     // edge half: 0 or 1
    const float* hf = outbuf + (size_t)N_NODES * H;

    for (int g = t0 + blockIdx.x; g < tN; g += gridDim.x) {
        int b = bBase;
        while (b < bBase + bCnt - 1 && g >= g_etile[b + 1]) b++;
        const int gi = b % 3;
        const int estart = g_eoff[b] + (g - g_etile[b]) * MSG_TE;
        const int ne = min(MSG_TE, g_eoff[b + 1] - estart);
        const float* __restrict__ w1 = w1a + (size_t)gi * H2 * H;
        const float* __restrict__ w2 = w2a + (size_t)gi * H * H;
        const float* __restrict__ w3 = w3a + (size_t)gi * H * H;
        const float* __restrict__ tbl = g_hsl1 + (size_t)gi * 6 * H;

        if (tid < MSG_TE) {
            if (tid < ne) {
                int eid = g_elist[estart + tid];
                int src = ei[eid];
                ssrc[tid] = src;
                sdst[tid] = ei[N_EDGES + eid];
                sgt[tid] = gate[src];
            } else {
                ssrc[tid] = -1;
                sgt[tid] = 0;
            }
        }
        __syncthreads();

        float acc[16];
        // ---- layer 1: hsl1 table + hf GEMM -> h1buf ----
        for (int p = wrp; p < MSG_TE; p += 8) {
            int src = ssrc[p];
            float4 v = make_float4(0.f, 0.f, 0.f, 0.f);
            if (src >= 0) v = ((const float4*)(hf + (size_t)src * H))[lane];
            xbuf[p][lane] = v;
        }
#pragma unroll
        for (int e = 0; e < 16; e++) {
            int gt = sgt[eh * 16 + e];
            acc[e] = __ldg(&tbl[gt * H + c0]);
        }
        __syncthreads();
        {
            const float* w1b = w1 + (size_t)H * H;   // hf half: rows 128..255
            for (int k4 = 0; k4 < H / 4; k4++) {
                const float* wr = w1b + (k4 * 4) * H;
                float wa0 = wr[c0],         wa1 = wr[H + c0],
                      wa2 = wr[2 * H + c0], wa3 = wr[3 * H + c0];
#pragma unroll
                for (int e = 0; e < 16; e++) {
                    float4 x = xbuf[eh * 16 + e][k4];
                    acc[e] = fmaf(x.x, wa0, acc[e]); acc[e] = fmaf(x.y, wa1, acc[e]);
                    acc[e] = fmaf(x.z, wa2, acc[e]); acc[e] = fmaf(x.w, wa3, acc[e]);
                }
            }
            float bb = b1a[gi * H + c0];
            float* h1f = (float*)h1buf;
#pragma unroll
            for (int e = 0; e < 16; e++)
                h1f[(eh * 16 + e) * H + c0] = fmaxf(acc[e] + bb, 0.f);
        }
        __syncthreads();

        // ---- layer 2: h1buf -> h2 (stored in xbuf) ----
#pragma unroll
        for (int e = 0; e < 16; e++) acc[e] = 0.f;
        for (int k4 = 0; k4 < H / 4; k4++) {
            const float* wr = w2 + (k4 * 4) * H;
            float wa0 = wr[c0],         wa1 = wr[H + c0],
                  wa2 = wr[2 * H + c0], wa3 = wr[3 * H + c0];
#pragma unroll
            for (int e = 0; e < 16; e++) {
                float4 x = h1buf[eh * 16 + e][k4];
                acc[e] = fmaf(x.x, wa0, acc[e]); acc[e] = fmaf(x.y, wa1, acc[e]);
                acc[e] = fmaf(x.z, wa2, acc[e]); acc[e] = fmaf(x.w, wa3, acc[e]);
            }
        }
        __syncthreads();
        {
            float bb = b2a[gi * H + c0];
            float* h2f = (float*)xbuf;
#pragma unroll
            for (int e = 0; e < 16; e++)
                h2f[(eh * 16 + e) * H + c0] = fmaxf(acc[e] + bb, 0.f);
        }
        __syncthreads();

        // ---- layer 3: xbuf(h2) -> scatter-add ----
#pragma unroll
        for (int e = 0; e < 16; e++) acc[e] = 0.f;
        for (int k4 = 0; k4 < H / 4; k4++) {
            const float* wr = w3 + (k4 * 4) * H;
            float wa0 = wr[c0],         wa1 = wr[H + c0],
                  wa2 = wr[2 * H + c0], wa3 = wr[3 * H + c0];
#pragma unroll
            for (int e = 0; e < 16; e++) {
                float4 x = xbuf[eh * 16 + e][k4];
                acc[e] = fmaf(x.x, wa0, acc[e]); acc[e] = fmaf(x.y, wa1, acc[e]);
                acc[e] = fmaf(x.z, wa2, acc[e]); acc[e] = fmaf(x.w, wa3, acc[e]);
            }
        }
        {
            float bb = b3a[gi * H + c0];
            for (int e = 0; e < 16; e++) {
                int ge = eh * 16 + e;
                if (ge < ne)
                    atomicAdd(&g_msg[(size_t)sdst[ge] * H + c0], acc[e] + bb);
            }
        }
        __syncthreads();
    }
}

// ---------------- per-level GRU kernel (+ z1 table apply) ------------------
// msg_total[node] = g_msg[node] (z0 part) + sum_gt z1cnt[node][gt]*mout[gi][gt].
// h_old provably zero: whh GEMM -> bhh bias. Counts self-reset after use.
__global__ void __launch_bounds__(128) k_gru_lvl(
        const float* __restrict__ bih_a, const float* __restrict__ bhh_a,
        float* __restrict__ outbuf, int lvl) {
    __shared__ float4 ms4[GRU_TN][H / 4];    // 8 KB
    __shared__ int snode[GRU_TN];
    __shared__ int scnt[GRU_TN][6];

    const int b0 = (lvl - 1) * 3;
    const int t0 = g_ntile[b0];
    const int t3 = g_ntile[b0 + 3];
    const int tid = threadIdx.x;
    const int lane = tid & 31, wrp = tid >> 5;
    const int j = tid;
    float* hf = outbuf + (size_t)N_NODES * H;

    for (int g = t0 + blockIdx.x; g < t3; g += gridDim.x) {
        int b = b0;
        while (b < b0 + 2 && g >= g_ntile[b + 1]) b++;
        const int gi = b - b0;
        const int nstart = g_noff[b] + (g - g_ntile[b]) * GRU_TN;
        const int nn = min(GRU_TN, g_noff[b + 1] - nstart);
        const float* __restrict__ wihT = g_wihT + (size_t)gi * H * H3;
        const float4* __restrict__ mo4 = (const float4*)g_mout + (size_t)gi * 6 * (H / 4);

        if (tid < GRU_TN)
            snode[tid] = (tid < nn) ? g_nlist[nstart + tid] : -1;
        __syncthreads();

        // stage + self-reset z1 counts
        if (tid < GRU_TN * 6) {
            int p = tid / 6, gt = tid - p * 6;
            int nd = snode[p];
            int c = 0;
            if (nd >= 0) {
                c = g_z1cnt[(size_t)nd * 6 + gt];
                if (c) g_z1cnt[(size_t)nd * 6 + gt] = 0;
            }
            scnt[p][gt] = c;
        }
        __syncthreads();

        for (int p = wrp; p < GRU_TN; p += 4) {
            int node = snode[p];
            float4 v = make_float4(0.f, 0.f, 0.f, 0.f);
            if (node >= 0) {
                v = ((const float4*)(g_msg + (size_t)node * H))[lane];
#pragma unroll
                for (int gt = 0; gt < 6; gt++) {
                    int c = scnt[p][gt];
                    if (c) {
                        float fc = (float)c;
                        float4 t = mo4[gt * (H / 4) + lane];
                        v.x = fmaf(fc, t.x, v.x);
                        v.y = fmaf(fc, t.y, v.y);
                        v.z = fmaf(fc, t.z, v.z);
                        v.w = fmaf(fc, t.w, v.w);
                    }
                }
            }
            ms4[p][lane] = v;
        }
        __syncthreads();

        float ar[GRU_TN], az[GRU_TN], an[GRU_TN];
#pragma unroll
        for (int e = 0; e < GRU_TN; e++) { ar[e] = 0.f; az[e] = 0.f; an[e] = 0.f; }

        for (int k4 = 0; k4 < H / 4; k4++) {
            const float* wr = wihT + (size_t)(k4 * 4) * H3;
            float r0 = wr[j],            r1 = wr[H3 + j],
                  r2 = wr[2 * H3 + j],   r3 = wr[3 * H3 + j];
            float z0 = wr[H + j],           z1 = wr[H3 + H + j],
                  z2 = wr[2 * H3 + H + j],  z3 = wr[3 * H3 + H + j];
            float n0 = wr[2 * H + j],          n1 = wr[H3 + 2 * H + j],
                  n2 = wr[2 * H3 + 2 * H + j], n3 = wr[3 * H3 + 2 * H + j];
#pragma unroll
            for (int e = 0; e < GRU_TN; e++) {
                float4 m = ms4[e][k4];
                ar[e] = fmaf(m.x, r0, ar[e]); ar[e] = fmaf(m.y, r1, ar[e]);
                ar[e] = fmaf(m.z, r2, ar[e]); ar[e] = fmaf(m.w, r3, ar[e]);
                az[e] = fmaf(m.x, z0, az[e]); az[e] = fmaf(m.y, z1, az[e]);
                az[e] = fmaf(m.z, z2, az[e]); az[e] = fmaf(m.w, z3, az[e]);
                an[e] = fmaf(m.x, n0, an[e]); an[e] = fmaf(m.y, n1, an[e]);
                an[e] = fmaf(m.z, n2, an[e]); an[e] = fmaf(m.w, n3, an[e]);
            }
        }

        const float bir = bih_a[gi * H3 + j]     + bhh_a[gi * H3 + j];
        const float biz = bih_a[gi * H3 + H + j] + bhh_a[gi * H3 + H + j];
        const float bin_ = bih_a[gi * H3 + 2 * H + j];
        const float bhn  = bhh_a[gi * H3 + 2 * H + j];
        for (int e = 0; e < GRU_TN; e++) {
            int node = snode[e];
            if (node >= 0) {
                float r = 1.0f / (1.0f + expf(-(ar[e] + bir)));
                float z = 1.0f / (1.0f + expf(-(az[e] + biz)));
                float nst = tanhf(an[e] + bin_ + r * bhn);
                hf[(size_t)node * H + j] = (1.0f - z) * nst;
            }
        }
        __syncthreads();
    }
}

// ---------------- launch ---------------------------------------------------

extern "C" void kernel_launch(void* const* d_in, const int* in_sizes, int n_in,
                              void* d_out, int out_size) {
    const int* gate    = (const int*)d_in[0];
    const int* flevel  = (const int*)d_in[1];
    const int* ei      = (const int*)d_in[2];
    const float* Ws    = (const float*)d_in[3];
    const float* Wt    = (const float*)d_in[4];
    const float* hs_W  = (const float*)d_in[5];
    const float* hs_b  = (const float*)d_in[6];
    const float* w1    = (const float*)d_in[7];
    const float* b1    = (const float*)d_in[8];
    const float* w2    = (const float*)d_in[9];
    const float* b2    = (const float*)d_in[10];
    const float* w3    = (const float*)d_in[11];
    const float* b3    = (const float*)d_in[12];
    const float* wih   = (const float*)d_in[13];
    const float* bih   = (const float*)d_in[15];
    const float* bhh   = (const float*)d_in[16];
    float* out = (float*)d_out;

    k_setup0<<<1030, 256>>>(Ws, Wt, hs_W, hs_b, wih, ei, gate, flevel);
    k_setup1<<<18, 128>>>(w1);
    k_setup2<<<2080, 256>>>((float4*)out, gate, ei, flevel, b1, w2, b2, w3, b3);

    for (int lvl = 1; lvl <= NLVL; lvl++) {
        if (lvl >= 2)   // level 1 has no z0 edges (hf of any src still zero)
            k_msg_range<<<592, 256>>>(ei, gate, out, w1, b1, w2, b2, w3, b3,
                                      (lvl - 1) * 3, 3);
        k_gru_lvl<<<1184, 128>>>(bih, bhh, out, lvl);
    }
}